// round 1
// baseline (speedup 1.0000x reference)
#include <cuda_runtime.h>
#include <math.h>

// ---------------- problem constants (fixed by setup_inputs) ----------------
#define Bc   2
#define Sq   1024
#define Dm   1024
#define Hh   16
#define DHd  64
#define Ex   8
#define FFd  4096
#define BH   (Bc*Hh)     // 32
#define ROWS (Bc*Sq)     // 2048
#define QK_SCALE 10.0f

// ---------------- scratch (device globals: allocation-free) ----------------
__device__ float g_h1[ROWS*Dm];
__device__ float g_qf[ROWS*Dm];
__device__ float g_kf[ROWS*Dm];
__device__ float g_vf[ROWS*Dm];
__device__ float g_qn[BH*Sq*DHd];
__device__ float g_kn[BH*Sq*DHd];
__device__ float g_vn[BH*Sq*DHd];
__device__ float g_logits[(size_t)BH*Sq*Sq];   // 128 MB, softmax done in-place
__device__ float g_ao[ROWS*Dm];
__device__ float g_o[ROWS*Dm];
__device__ float g_h2[ROWS*Dm];
__device__ float g_gate[ROWS*Ex];
__device__ float g_hid[ROWS*FFd];
__device__ float g_moe[ROWS*Dm];

// ---------------- helpers ----------------
__device__ __forceinline__ float gelu_f(float x) {
    // jax.nn.gelu default (approximate=True, tanh form)
    float x3 = x * x * x;
    float t  = tanhf(0.7978845608028654f * (x + 0.044715f * x3));
    return 0.5f * x * (1.0f + t);
}

// ---------------- LayerNorm: one block per row ----------------
__global__ void ln_kernel(const float* __restrict__ x, const float* __restrict__ g,
                          const float* __restrict__ b, float* __restrict__ y)
{
    __shared__ float buf[Dm];
    __shared__ float red[256];
    const int row = blockIdx.x;
    const int tid = threadIdx.x;
    const float* xr = x + (size_t)row * Dm;

    float s = 0.f;
    for (int i = tid; i < Dm; i += 256) { float v = xr[i]; buf[i] = v; s += v; }
    red[tid] = s; __syncthreads();
    for (int off = 128; off > 0; off >>= 1) {
        if (tid < off) red[tid] += red[tid + off];
        __syncthreads();
    }
    const float mean = red[0] * (1.0f / Dm);
    __syncthreads();

    float s2 = 0.f;
    for (int i = tid; i < Dm; i += 256) { float d = buf[i] - mean; s2 += d * d; }
    red[tid] = s2; __syncthreads();
    for (int off = 128; off > 0; off >>= 1) {
        if (tid < off) red[tid] += red[tid + off];
        __syncthreads();
    }
    const float var = red[0] * (1.0f / Dm);
    const float inv = rsqrtf(var + 1e-5f);

    float* yr = y + (size_t)row * Dm;
    for (int i = tid; i < Dm; i += 256)
        yr[i] = (buf[i] - mean) * inv * g[i] + b[i];
}

// ---------------- SGEMM: C[M,N] = A[M,K] @ B[K,N]  (dims % 128 == 0, K % 8 == 0)
// epi 0: plain store; epi 1: gelu(acc + bias[col]); epi 2: C += gate[row,e]*(acc+bias[col])
__global__ void __launch_bounds__(256)
sgemm_kernel(const float* __restrict__ A, const float* __restrict__ B,
             float* __restrict__ C, int M, int N, int K,
             int epi, const float* __restrict__ bias,
             const float* __restrict__ gate, int expert)
{
    __shared__ float As[8][128];
    __shared__ float Bs[8][128];
    const int tid = threadIdx.x;
    const int bm  = blockIdx.y * 128;
    const int bn  = blockIdx.x * 128;
    const int aRow = tid >> 1;
    const int aCol = (tid & 1) << 2;
    const int bRow = tid >> 5;
    const int bCol = (tid & 31) << 2;
    const int ty = (tid >> 4) << 3;
    const int tx = (tid & 15) << 3;

    const float* Aptr = A + (size_t)(bm + aRow) * K + aCol;
    const float* Bptr = B + (size_t)bRow * N + bn + bCol;

    float acc[8][8];
    #pragma unroll
    for (int i = 0; i < 8; i++)
        #pragma unroll
        for (int j = 0; j < 8; j++) acc[i][j] = 0.f;

    for (int k0 = 0; k0 < K; k0 += 8) {
        float4 av = *(const float4*)(Aptr + k0);
        float4 bv = *(const float4*)(Bptr + (size_t)k0 * N);
        As[aCol+0][aRow] = av.x;
        As[aCol+1][aRow] = av.y;
        As[aCol+2][aRow] = av.z;
        As[aCol+3][aRow] = av.w;
        *(float4*)&Bs[bRow][bCol] = bv;
        __syncthreads();

        #pragma unroll
        for (int k = 0; k < 8; k++) {
            float ar[8], br[8];
            *(float4*)&ar[0] = *(const float4*)&As[k][ty];
            *(float4*)&ar[4] = *(const float4*)&As[k][ty + 4];
            *(float4*)&br[0] = *(const float4*)&Bs[k][tx];
            *(float4*)&br[4] = *(const float4*)&Bs[k][tx + 4];
            #pragma unroll
            for (int i = 0; i < 8; i++)
                #pragma unroll
                for (int j = 0; j < 8; j++)
                    acc[i][j] = fmaf(ar[i], br[j], acc[i][j]);
        }
        __syncthreads();
    }

    if (epi == 0) {
        #pragma unroll
        for (int i = 0; i < 8; i++) {
            const size_t base = (size_t)(bm + ty + i) * N + bn + tx;
            *(float4*)&C[base]     = make_float4(acc[i][0], acc[i][1], acc[i][2], acc[i][3]);
            *(float4*)&C[base + 4] = make_float4(acc[i][4], acc[i][5], acc[i][6], acc[i][7]);
        }
    } else if (epi == 1) {
        #pragma unroll
        for (int i = 0; i < 8; i++) {
            const size_t base = (size_t)(bm + ty + i) * N + bn + tx;
            #pragma unroll
            for (int j = 0; j < 8; j++)
                C[base + j] = gelu_f(acc[i][j] + bias[bn + tx + j]);
        }
    } else {
        #pragma unroll
        for (int i = 0; i < 8; i++) {
            const float gv = gate[(size_t)(bm + ty + i) * Ex + expert];
            const size_t base = (size_t)(bm + ty + i) * N + bn + tx;
            #pragma unroll
            for (int j = 0; j < 8; j++)
                C[base + j] += gv * (acc[i][j] + bias[bn + tx + j]);
        }
    }
}

// ---------------- l2norm over head dim + scale + transpose to [B,H,S,DH] ----
__global__ void l2n_kernel(const float* __restrict__ in, const float* __restrict__ scale,
                           float* __restrict__ out)
{
    const int r    = blockIdx.x * 8 + (threadIdx.x >> 5);   // 0..BH*Sq-1, = (b*H+h)*S+s
    const int lane = threadIdx.x & 31;
    const int b = r / (Hh * Sq);
    const int h = (r / Sq) % Hh;
    const int s = r % Sq;
    const float* src = in + ((size_t)(b * Sq + s)) * Dm + h * DHd;
    float v0 = src[lane], v1 = src[lane + 32];
    float ss = v0 * v0 + v1 * v1;
    #pragma unroll
    for (int o = 16; o; o >>= 1) ss += __shfl_xor_sync(0xffffffffu, ss, o);
    const float inv = rsqrtf(ss + 1e-12f);
    float* dst = out + (size_t)r * DHd;
    dst[lane]      = v0 * inv * scale[h * DHd + lane];
    dst[lane + 32] = v1 * inv * scale[h * DHd + lane + 32];
}

// ---------------- V transpose [B,S,H*DH] -> [B,H,S,DH] ----------------
__global__ void vtrans_kernel(const float* __restrict__ in, float* __restrict__ out)
{
    const int idx = blockIdx.x * 256 + threadIdx.x;   // 2^21 total
    const int d = idx & 63;
    const int s = (idx >> 6) & 1023;
    const int h = (idx >> 16) & 15;
    const int b = idx >> 20;
    out[idx] = in[((size_t)(b * Sq + s)) * Dm + h * DHd + d];
}

// ---------------- QK^T (lower-triangle tiles only), scaled by 10 ----------
__global__ void __launch_bounds__(256)
qk_kernel(const float* __restrict__ qn, const float* __restrict__ kn,
          float* __restrict__ logits)
{
    const int jt = blockIdx.x, it = blockIdx.y, bh = blockIdx.z;
    if (jt > it) return;
    __shared__ float qs[64][65];
    __shared__ float ks[64][65];
    const float* qb = qn + ((size_t)bh * Sq + it * 64) * DHd;
    const float* kb = kn + ((size_t)bh * Sq + jt * 64) * DHd;
    const int tid = threadIdx.x;

    #pragma unroll
    for (int t = 0; t < 4; t++) {
        const int slot = tid + t * 256;
        const int r = slot >> 4, c4 = (slot & 15) << 2;
        float4 qv = *(const float4*)(qb + r * DHd + c4);
        qs[r][c4] = qv.x; qs[r][c4+1] = qv.y; qs[r][c4+2] = qv.z; qs[r][c4+3] = qv.w;
        float4 kv = *(const float4*)(kb + r * DHd + c4);
        ks[r][c4] = kv.x; ks[r][c4+1] = kv.y; ks[r][c4+2] = kv.z; ks[r][c4+3] = kv.w;
    }
    __syncthreads();

    const int ty = (tid >> 4) << 2;
    const int tx = (tid & 15) << 2;
    float acc[4][4] = {};
    #pragma unroll 16
    for (int k = 0; k < 64; k++) {
        float a0 = qs[ty][k],   a1 = qs[ty+1][k], a2 = qs[ty+2][k], a3 = qs[ty+3][k];
        float b0 = ks[tx][k],   b1 = ks[tx+1][k], b2 = ks[tx+2][k], b3 = ks[tx+3][k];
        acc[0][0] = fmaf(a0,b0,acc[0][0]); acc[0][1] = fmaf(a0,b1,acc[0][1]);
        acc[0][2] = fmaf(a0,b2,acc[0][2]); acc[0][3] = fmaf(a0,b3,acc[0][3]);
        acc[1][0] = fmaf(a1,b0,acc[1][0]); acc[1][1] = fmaf(a1,b1,acc[1][1]);
        acc[1][2] = fmaf(a1,b2,acc[1][2]); acc[1][3] = fmaf(a1,b3,acc[1][3]);
        acc[2][0] = fmaf(a2,b0,acc[2][0]); acc[2][1] = fmaf(a2,b1,acc[2][1]);
        acc[2][2] = fmaf(a2,b2,acc[2][2]); acc[2][3] = fmaf(a2,b3,acc[2][3]);
        acc[3][0] = fmaf(a3,b0,acc[3][0]); acc[3][1] = fmaf(a3,b1,acc[3][1]);
        acc[3][2] = fmaf(a3,b2,acc[3][2]); acc[3][3] = fmaf(a3,b3,acc[3][3]);
    }
    #pragma unroll
    for (int i = 0; i < 4; i++) {
        const size_t base = ((size_t)bh * Sq + it * 64 + ty + i) * Sq + jt * 64 + tx;
        #pragma unroll
        for (int j = 0; j < 4; j++)
            logits[base + j] = acc[i][j] * QK_SCALE;
    }
}

// ---------------- causal row softmax, in place; zero-fills masked cols -----
__global__ void softmax_kernel(float* __restrict__ l)
{
    const int row = blockIdx.x;        // bh*Sq + i
    const int i   = row & (Sq - 1);
    const int n   = i + 1;
    float* p = l + (size_t)row * Sq;
    __shared__ float red[128];
    const int tid = threadIdx.x;

    float m = -1e30f;
    for (int j = tid; j < n; j += 128) m = fmaxf(m, p[j]);
    red[tid] = m; __syncthreads();
    for (int off = 64; off > 0; off >>= 1) {
        if (tid < off) red[tid] = fmaxf(red[tid], red[tid + off]);
        __syncthreads();
    }
    m = red[0]; __syncthreads();

    float s = 0.f;
    for (int j = tid; j < n; j += 128) s += expf(p[j] - m);
    red[tid] = s; __syncthreads();
    for (int off = 64; off > 0; off >>= 1) {
        if (tid < off) red[tid] += red[tid + off];
        __syncthreads();
    }
    const float inv = 1.0f / red[0];

    for (int j = tid; j < Sq; j += 128)
        p[j] = (j < n) ? expf(p[j] - m) * inv : 0.f;
}

// ---------------- P@V per (bh, query tile), causal-restricted K loop -------
__global__ void __launch_bounds__(256)
pv_kernel(const float* __restrict__ attn, const float* __restrict__ vn,
          float* __restrict__ ao)
{
    const int it = blockIdx.x;
    const int bh = blockIdx.y;
    const int b = bh >> 4, h = bh & 15;
    __shared__ float as_[64][65];
    __shared__ float vs[64][65];
    const int tid = threadIdx.x;
    const int ty = (tid >> 4) << 2;
    const int tx = (tid & 15) << 2;
    float acc[4][4] = {};

    for (int kt = 0; kt <= it; kt++) {
        const float* ab = attn + ((size_t)bh * Sq + it * 64) * Sq + kt * 64;
        const float* vb = vn   + ((size_t)bh * Sq + kt * 64) * DHd;
        #pragma unroll
        for (int t = 0; t < 4; t++) {
            const int slot = tid + t * 256;
            const int r = slot >> 4, c4 = (slot & 15) << 2;
            float4 av = *(const float4*)(ab + (size_t)r * Sq + c4);
            as_[r][c4] = av.x; as_[r][c4+1] = av.y; as_[r][c4+2] = av.z; as_[r][c4+3] = av.w;
            float4 vv = *(const float4*)(vb + r * DHd + c4);
            vs[r][c4] = vv.x; vs[r][c4+1] = vv.y; vs[r][c4+2] = vv.z; vs[r][c4+3] = vv.w;
        }
        __syncthreads();

        #pragma unroll 16
        for (int k = 0; k < 64; k++) {
            float a0 = as_[ty][k], a1 = as_[ty+1][k], a2 = as_[ty+2][k], a3 = as_[ty+3][k];
            float b0 = vs[k][tx], b1 = vs[k][tx+1], b2 = vs[k][tx+2], b3 = vs[k][tx+3];
            acc[0][0] = fmaf(a0,b0,acc[0][0]); acc[0][1] = fmaf(a0,b1,acc[0][1]);
            acc[0][2] = fmaf(a0,b2,acc[0][2]); acc[0][3] = fmaf(a0,b3,acc[0][3]);
            acc[1][0] = fmaf(a1,b0,acc[1][0]); acc[1][1] = fmaf(a1,b1,acc[1][1]);
            acc[1][2] = fmaf(a1,b2,acc[1][2]); acc[1][3] = fmaf(a1,b3,acc[1][3]);
            acc[2][0] = fmaf(a2,b0,acc[2][0]); acc[2][1] = fmaf(a2,b1,acc[2][1]);
            acc[2][2] = fmaf(a2,b2,acc[2][2]); acc[2][3] = fmaf(a2,b3,acc[2][3]);
            acc[3][0] = fmaf(a3,b0,acc[3][0]); acc[3][1] = fmaf(a3,b1,acc[3][1]);
            acc[3][2] = fmaf(a3,b2,acc[3][2]); acc[3][3] = fmaf(a3,b3,acc[3][3]);
        }
        __syncthreads();
    }

    #pragma unroll
    for (int i = 0; i < 4; i++) {
        const size_t base = ((size_t)(b * Sq + it * 64 + ty + i)) * Dm + h * DHd + tx;
        #pragma unroll
        for (int j = 0; j < 4; j++)
            ao[base + j] = acc[i][j];
    }
}

// ---------------- gate: softmax(h2 @ gate_w + gate_b) over E=8 -------------
__global__ void gate_kernel(const float* __restrict__ h2, const float* __restrict__ gw,
                            const float* __restrict__ gb, float* __restrict__ gate)
{
    const int row = blockIdx.x;
    const int tid = threadIdx.x;
    const int e = tid >> 5, lane = tid & 31;
    const float* hr = h2 + (size_t)row * Dm;
    float s = 0.f;
    for (int k = lane; k < Dm; k += 32) s += hr[k] * gw[k * Ex + e];
    #pragma unroll
    for (int o = 16; o; o >>= 1) s += __shfl_xor_sync(0xffffffffu, s, o);
    __shared__ float lg[Ex];
    if (lane == 0) lg[e] = s + gb[e];
    __syncthreads();
    if (tid == 0) {
        float m = lg[0];
        #pragma unroll
        for (int q = 1; q < Ex; q++) m = fmaxf(m, lg[q]);
        float ex[Ex], sum = 0.f;
        #pragma unroll
        for (int q = 0; q < Ex; q++) { ex[q] = expf(lg[q] - m); sum += ex[q]; }
        const float inv = 1.0f / sum;
        #pragma unroll
        for (int q = 0; q < Ex; q++) gate[(size_t)row * Ex + q] = ex[q] * inv;
    }
}

// ---------------- launch ----------------
extern "C" void kernel_launch(void* const* d_in, const int* in_sizes, int n_in,
                              void* d_out, int out_size)
{
    const float* x       = (const float*)d_in[0];
    const float* ln_g    = (const float*)d_in[1];
    const float* ln_b    = (const float*)d_in[2];
    const float* Wq      = (const float*)d_in[3];
    const float* Wk      = (const float*)d_in[4];
    const float* Wv      = (const float*)d_in[5];
    const float* q_scale = (const float*)d_in[6];
    const float* k_scale = (const float*)d_in[7];
    const float* Wo      = (const float*)d_in[8];
    const float* gate_w  = (const float*)d_in[9];
    const float* gate_b  = (const float*)d_in[10];
    const float* w1      = (const float*)d_in[11];
    const float* b1      = (const float*)d_in[12];
    const float* w2      = (const float*)d_in[13];
    const float* b2      = (const float*)d_in[14];
    float* out = (float*)d_out;

    float *h1, *qf, *kf, *vf, *qn, *kn, *vn, *logits, *ao, *o, *h2, *gate, *hid, *moe;
    cudaGetSymbolAddress((void**)&h1,     g_h1);
    cudaGetSymbolAddress((void**)&qf,     g_qf);
    cudaGetSymbolAddress((void**)&kf,     g_kf);
    cudaGetSymbolAddress((void**)&vf,     g_vf);
    cudaGetSymbolAddress((void**)&qn,     g_qn);
    cudaGetSymbolAddress((void**)&kn,     g_kn);
    cudaGetSymbolAddress((void**)&vn,     g_vn);
    cudaGetSymbolAddress((void**)&logits, g_logits);
    cudaGetSymbolAddress((void**)&ao,     g_ao);
    cudaGetSymbolAddress((void**)&o,      g_o);
    cudaGetSymbolAddress((void**)&h2,     g_h2);
    cudaGetSymbolAddress((void**)&gate,   g_gate);
    cudaGetSymbolAddress((void**)&hid,    g_hid);
    cudaGetSymbolAddress((void**)&moe,    g_moe);

    const dim3 g_1024(Dm / 128, ROWS / 128);   // (8,16)
    const dim3 g_4096(FFd / 128, ROWS / 128);  // (32,16)

    // 1. pre-attention LN
    ln_kernel<<<ROWS, 256>>>(x, ln_g, ln_b, h1);

    // 2. QKV projections
    sgemm_kernel<<<g_1024, 256>>>(h1, Wq, qf, ROWS, Dm, Dm, 0, nullptr, nullptr, 0);
    sgemm_kernel<<<g_1024, 256>>>(h1, Wk, kf, ROWS, Dm, Dm, 0, nullptr, nullptr, 0);
    sgemm_kernel<<<g_1024, 256>>>(h1, Wv, vf, ROWS, Dm, Dm, 0, nullptr, nullptr, 0);

    // 3. l2norm+scale+transpose for q,k; transpose v
    l2n_kernel<<<(BH * Sq) / 8, 256>>>(qf, q_scale, qn);
    l2n_kernel<<<(BH * Sq) / 8, 256>>>(kf, k_scale, kn);
    vtrans_kernel<<<(BH * Sq * DHd) / 256, 256>>>(vf, vn);

    // 4. attention
    qk_kernel<<<dim3(Sq / 64, Sq / 64, BH), 256>>>(qn, kn, logits);
    softmax_kernel<<<BH * Sq, 128>>>(logits);
    pv_kernel<<<dim3(Sq / 64, BH), 256>>>(logits, vn, ao);

    // 5. output projection + mid LN
    sgemm_kernel<<<g_1024, 256>>>(ao, Wo, o, ROWS, Dm, Dm, 0, nullptr, nullptr, 0);
    ln_kernel<<<ROWS, 256>>>(o, ln_g, ln_b, h2);

    // 6. gate
    gate_kernel<<<ROWS, 256>>>(h2, gate_w, gate_b, gate);

    // 7. dense MoE: loop experts, accumulate gated expert outputs into moe
    cudaMemsetAsync(moe, 0, (size_t)ROWS * Dm * sizeof(float), 0);
    for (int e = 0; e < Ex; e++) {
        sgemm_kernel<<<g_4096, 256>>>(h2, w1 + (size_t)e * Dm * FFd, hid,
                                      ROWS, FFd, Dm, 1, b1 + (size_t)e * FFd, nullptr, 0);
        sgemm_kernel<<<g_1024, 256>>>(hid, w2 + (size_t)e * FFd * Dm, moe,
                                      ROWS, Dm, FFd, 2, b2 + (size_t)e * Dm, gate, e);
    }

    // 8. final LN -> output
    ln_kernel<<<ROWS, 256>>>(moe, ln_g, ln_b, out);
}

// round 3
// speedup vs baseline: 3.5679x; 3.5679x over previous
#include <cuda_runtime.h>
#include <cuda_bf16.h>
#include <math.h>
#include <stdint.h>

// ---------------- problem constants ----------------
#define Bc   2
#define Sq   1024
#define Dm   1024
#define Hh   16
#define DHd  64
#define Ex   8
#define FFd  4096
#define BH   (Bc*Hh)     // 32
#define ROWS (Bc*Sq)     // 2048
#define QK_SCALE 10.0f

// GEMM tiling
#define BM 128
#define BN 128
#define BK 64
#define LDS 72                      // BK + 8 pad (bf16 units)
#define MAT_BYTES (128*LDS*2)       // 18432 bytes per 128x64 tile
#define STAGE_BYTES (4*MAT_BYTES)   // Ahi,Alo,Bhi,Blo
#define SMEM_TOTAL_G (2*STAGE_BYTES) // 147456

// ---------------- low-level helpers ----------------
__device__ __forceinline__ uint32_t smem_u32(const void* p) {
    uint32_t a;
    asm("{ .reg .u64 t; cvta.to.shared.u64 t, %1; cvt.u32.u64 %0, t; }" : "=r"(a) : "l"(p));
    return a;
}
__device__ __forceinline__ void cp16(uint32_t dst, const void* src) {
    asm volatile("cp.async.cg.shared.global [%0], [%1], 16;" :: "r"(dst), "l"(src));
}
#define CP_COMMIT() asm volatile("cp.async.commit_group;" ::: "memory")
#define CP_WAIT(n)  asm volatile("cp.async.wait_group %0;" :: "n"(n) : "memory")

#define LDSM_X4(r0, r1, r2, r3, addr) \
    asm volatile("ldmatrix.sync.aligned.m8n8.x4.shared.b16 {%0,%1,%2,%3}, [%4];" \
        : "=r"(r0), "=r"(r1), "=r"(r2), "=r"(r3) : "r"(addr))

#define MMA_BF16(d, a, b0, b1) \
    asm volatile("mma.sync.aligned.m16n8k16.row.col.f32.bf16.bf16.f32 " \
        "{%0,%1,%2,%3}, {%4,%5,%6,%7}, {%8,%9}, {%0,%1,%2,%3};" \
        : "+f"((d)[0]), "+f"((d)[1]), "+f"((d)[2]), "+f"((d)[3]) \
        : "r"((a)[0]), "r"((a)[1]), "r"((a)[2]), "r"((a)[3]), "r"(b0), "r"(b1))

// ---------------- scratch (device globals) ----------------
__device__ __nv_bfloat16 g_h1hi[ROWS*Dm], g_h1lo[ROWS*Dm];
__device__ float g_qkvf[ROWS*3*Dm];
__device__ float g_qn[BH*Sq*DHd], g_kn[BH*Sq*DHd], g_vn[BH*Sq*DHd];
__device__ float g_logits[(size_t)BH*Sq*Sq];
__device__ __nv_bfloat16 g_aohi[ROWS*Dm], g_aolo[ROWS*Dm];
__device__ float g_o[ROWS*Dm], g_h2[ROWS*Dm];
__device__ __nv_bfloat16 g_h2hi[ROWS*Dm], g_h2lo[ROWS*Dm];
__device__ float g_gate[ROWS*Ex];
__device__ __nv_bfloat16 g_hidhi[(size_t)Ex*ROWS*FFd], g_hidlo[(size_t)Ex*ROWS*FFd];
__device__ float g_expout[(size_t)Ex*ROWS*Dm];
__device__ __nv_bfloat16 g_wqkvThi[3*Dm*Dm], g_wqkvTlo[3*Dm*Dm];
__device__ __nv_bfloat16 g_woThi[Dm*Dm], g_woTlo[Dm*Dm];
__device__ __nv_bfloat16 g_w1Thi[(size_t)Ex*FFd*Dm], g_w1Tlo[(size_t)Ex*FFd*Dm];
__device__ __nv_bfloat16 g_w2Thi[(size_t)Ex*Dm*FFd], g_w2Tlo[(size_t)Ex*Dm*FFd];

// ---------------- math helpers ----------------
__device__ __forceinline__ float gelu_f(float x) {
    float x3 = x * x * x;
    float t  = tanhf(0.7978845608028654f * (x + 0.044715f * x3));
    return 0.5f * x * (1.0f + t);
}

// ---------------- weight transpose + bf16 split: W[K,N] -> hi/lo [N,K] ------
__global__ void wprep_kernel(const float* __restrict__ W, __nv_bfloat16* __restrict__ hi,
                             __nv_bfloat16* __restrict__ lo, int K, int N)
{
    __shared__ float t[32][33];
    const size_t zoff = (size_t)blockIdx.z * K * N;
    const int k0 = blockIdx.y * 32, n0 = blockIdx.x * 32;
    const int tx = threadIdx.x, ty = threadIdx.y; // 32 x 8
    #pragma unroll
    for (int i = 0; i < 4; i++)
        t[ty + 8*i][tx] = W[zoff + (size_t)(k0 + ty + 8*i) * N + n0 + tx];
    __syncthreads();
    #pragma unroll
    for (int i = 0; i < 4; i++) {
        float v = t[tx][ty + 8*i];
        const size_t o = zoff + (size_t)(n0 + ty + 8*i) * K + k0 + tx;
        __nv_bfloat16 h = __float2bfloat16(v);
        hi[o] = h;
        lo[o] = __float2bfloat16(v - __bfloat162float(h));
    }
}

// ---------------- LayerNorm (optional fp32 + hi/lo outputs) ----------------
__global__ void ln_kernel(const float* __restrict__ x, const float* __restrict__ g,
                          const float* __restrict__ b, float* __restrict__ yf,
                          __nv_bfloat16* __restrict__ yhi, __nv_bfloat16* __restrict__ ylo)
{
    __shared__ float buf[Dm];
    __shared__ float red[256];
    const int row = blockIdx.x;
    const int tid = threadIdx.x;
    const float* xr = x + (size_t)row * Dm;
    float s = 0.f;
    for (int i = tid; i < Dm; i += 256) { float v = xr[i]; buf[i] = v; s += v; }
    red[tid] = s; __syncthreads();
    for (int off = 128; off > 0; off >>= 1) { if (tid < off) red[tid] += red[tid+off]; __syncthreads(); }
    const float mean = red[0] * (1.0f / Dm);
    __syncthreads();
    float s2 = 0.f;
    for (int i = tid; i < Dm; i += 256) { float d = buf[i] - mean; s2 += d * d; }
    red[tid] = s2; __syncthreads();
    for (int off = 128; off > 0; off >>= 1) { if (tid < off) red[tid] += red[tid+off]; __syncthreads(); }
    const float inv = rsqrtf(red[0] * (1.0f / Dm) + 1e-5f);
    for (int i = tid; i < Dm; i += 256) {
        float v = (buf[i] - mean) * inv * g[i] + b[i];
        if (yf) yf[(size_t)row*Dm + i] = v;
        if (yhi) {
            __nv_bfloat16 h = __float2bfloat16(v);
            yhi[(size_t)row*Dm + i] = h;
            ylo[(size_t)row*Dm + i] = __float2bfloat16(v - __bfloat162float(h));
        }
    }
}

// ---------------- mma.sync bf16x3 GEMM: D[M,N] = A[M,K] @ B[N,K]^T ----------
// EPI 0: fp32 store; EPI 1: gelu(acc+bias) -> bf16 hi/lo; EPI 2: gate*(acc+bias) -> fp32
template<int EPI>
__global__ void __launch_bounds__(256, 1)
bgemm_kernel(const __nv_bfloat16* __restrict__ Ahi, const __nv_bfloat16* __restrict__ Alo,
             const __nv_bfloat16* __restrict__ Bhi, const __nv_bfloat16* __restrict__ Blo,
             int N, int K,
             long long az, long long bz, long long oz,
             float* __restrict__ outf,
             __nv_bfloat16* __restrict__ outhi, __nv_bfloat16* __restrict__ outlo,
             const float* __restrict__ bias, long long biasz,
             const float* __restrict__ gate)
{
    extern __shared__ char smem[];
    const uint32_t sbase = smem_u32(smem);
    const int tid  = threadIdx.x;
    const int wid  = tid >> 5;
    const int lane = tid & 31;
    const int wm   = wid >> 1;       // 0..3
    const int wn   = wid & 1;        // 0..1
    const int m0 = blockIdx.y * BM;
    const int n0 = blockIdx.x * BN;
    const int e  = blockIdx.z;

    const __nv_bfloat16* pAhi = Ahi + (size_t)e * az;
    const __nv_bfloat16* pAlo = Alo + (size_t)e * az;
    const __nv_bfloat16* pBhi = Bhi + (size_t)e * bz;
    const __nv_bfloat16* pBlo = Blo + (size_t)e * bz;

    // per-thread cp.async coordinates: 4 iterations, each covers 32 rows
    const int lrow = tid >> 3;            // 0..31
    const int lc8  = (tid & 7) * 8;       // bf16 col offset (16B chunk)

    float acc[2][8][4];
    #pragma unroll
    for (int i = 0; i < 2; i++)
        #pragma unroll
        for (int j = 0; j < 8; j++)
            #pragma unroll
            for (int q = 0; q < 4; q++) acc[i][j][q] = 0.f;

    const int NB = K / BK;

    // ---- prefetch stage 0 ----
    {
        const uint32_t so = sbase;
        #pragma unroll
        for (int i = 0; i < 4; i++) {
            const int row = lrow + i * 32;
            const uint32_t sa = so + (uint32_t)(row * LDS + lc8) * 2;
            const size_t ga = (size_t)(m0 + row) * K + lc8;
            const size_t gb = (size_t)(n0 + row) * K + lc8;
            cp16(sa,                 pAhi + ga);
            cp16(sa + MAT_BYTES,     pAlo + ga);
            cp16(sa + 2*MAT_BYTES,   pBhi + gb);
            cp16(sa + 3*MAT_BYTES,   pBlo + gb);
        }
        CP_COMMIT();
    }

    for (int kb = 0; kb < NB; kb++) {
        const int s = kb & 1;
        if (kb + 1 < NB) {
            const int kk = (kb + 1) * BK;
            const uint32_t so = sbase + (s ^ 1) * STAGE_BYTES;
            #pragma unroll
            for (int i = 0; i < 4; i++) {
                const int row = lrow + i * 32;
                const uint32_t sa = so + (uint32_t)(row * LDS + lc8) * 2;
                const size_t ga = (size_t)(m0 + row) * K + kk + lc8;
                const size_t gb = (size_t)(n0 + row) * K + kk + lc8;
                cp16(sa,                 pAhi + ga);
                cp16(sa + MAT_BYTES,     pAlo + ga);
                cp16(sa + 2*MAT_BYTES,   pBhi + gb);
                cp16(sa + 3*MAT_BYTES,   pBlo + gb);
            }
            CP_COMMIT();
            CP_WAIT(1);
        } else {
            CP_WAIT(0);
        }
        __syncthreads();

        const uint32_t so = sbase + s * STAGE_BYTES;
        #pragma unroll
        for (int k16 = 0; k16 < 4; k16++) {
            const int kc = k16 * 16;
            uint32_t ah[2][4], al[2][4], bh[4][4], bl[4][4];
            #pragma unroll
            for (int mt = 0; mt < 2; mt++) {
                const int arow = wm * 32 + mt * 16 + (lane & 15);
                const int acol = kc + ((lane >> 4) << 3);
                const uint32_t addr = so + (uint32_t)(arow * LDS + acol) * 2;
                LDSM_X4(ah[mt][0], ah[mt][1], ah[mt][2], ah[mt][3], addr);
                LDSM_X4(al[mt][0], al[mt][1], al[mt][2], al[mt][3], addr + MAT_BYTES);
            }
            #pragma unroll
            for (int p = 0; p < 4; p++) {
                const int nrow = wn * 64 + p * 16 + (lane & 7) + ((lane & 16) >> 1);
                const int ncol = kc + (lane & 8);
                const uint32_t addr = so + 2*MAT_BYTES + (uint32_t)(nrow * LDS + ncol) * 2;
                LDSM_X4(bh[p][0], bh[p][1], bh[p][2], bh[p][3], addr);
                LDSM_X4(bl[p][0], bl[p][1], bl[p][2], bl[p][3], addr + MAT_BYTES);
            }
            #pragma unroll
            for (int mt = 0; mt < 2; mt++) {
                #pragma unroll
                for (int nt = 0; nt < 8; nt++) {
                    const int pr = nt >> 1, ix = (nt & 1) * 2;
                    MMA_BF16(acc[mt][nt], ah[mt], bh[pr][ix], bh[pr][ix+1]);   // Ah*Bh
                    MMA_BF16(acc[mt][nt], al[mt], bh[pr][ix], bh[pr][ix+1]);   // Al*Bh
                    MMA_BF16(acc[mt][nt], ah[mt], bl[pr][ix], bl[pr][ix+1]);   // Ah*Bl
                }
            }
        }
        __syncthreads();
    }

    // ---- epilogue ----
    #pragma unroll
    for (int mt = 0; mt < 2; mt++) {
        const int rA = m0 + wm * 32 + mt * 16 + (lane >> 2);
        const int rB = rA + 8;
        float gv0 = 0.f, gv1 = 0.f;
        if (EPI == 2) {
            gv0 = gate[(size_t)rA * Ex + e];
            gv1 = gate[(size_t)rB * Ex + e];
        }
        #pragma unroll
        for (int nt = 0; nt < 8; nt++) {
            const int col = n0 + wn * 64 + nt * 8 + (lane & 3) * 2;
            float d0 = acc[mt][nt][0], d1 = acc[mt][nt][1];
            float d2 = acc[mt][nt][2], d3 = acc[mt][nt][3];
            if (EPI == 0) {
                *(float2*)(outf + (size_t)rA * N + col) = make_float2(d0, d1);
                *(float2*)(outf + (size_t)rB * N + col) = make_float2(d2, d3);
            } else if (EPI == 1) {
                const float b0 = bias[(size_t)e * biasz + col];
                const float b1 = bias[(size_t)e * biasz + col + 1];
                float v0 = gelu_f(d0 + b0), v1 = gelu_f(d1 + b1);
                float v2 = gelu_f(d2 + b0), v3 = gelu_f(d3 + b1);
                __nv_bfloat16 h0 = __float2bfloat16(v0), h1 = __float2bfloat16(v1);
                __nv_bfloat16 h2 = __float2bfloat16(v2), h3 = __float2bfloat16(v3);
                __nv_bfloat162 hhA; hhA.x = h0; hhA.y = h1;
                __nv_bfloat162 hhB; hhB.x = h2; hhB.y = h3;
                __nv_bfloat162 llA, llB;
                llA.x = __float2bfloat16(v0 - __bfloat162float(h0));
                llA.y = __float2bfloat16(v1 - __bfloat162float(h1));
                llB.x = __float2bfloat16(v2 - __bfloat162float(h2));
                llB.y = __float2bfloat16(v3 - __bfloat162float(h3));
                const size_t gA = (size_t)e * oz + (size_t)rA * N + col;
                const size_t gB = (size_t)e * oz + (size_t)rB * N + col;
                *(__nv_bfloat162*)(outhi + gA) = hhA;
                *(__nv_bfloat162*)(outlo + gA) = llA;
                *(__nv_bfloat162*)(outhi + gB) = hhB;
                *(__nv_bfloat162*)(outlo + gB) = llB;
            } else {
                const float b0 = bias[(size_t)e * biasz + col];
                const float b1 = bias[(size_t)e * biasz + col + 1];
                const size_t gA = (size_t)e * oz + (size_t)rA * N + col;
                const size_t gB = (size_t)e * oz + (size_t)rB * N + col;
                *(float2*)(outf + gA) = make_float2(gv0 * (d0 + b0), gv0 * (d1 + b1));
                *(float2*)(outf + gB) = make_float2(gv1 * (d2 + b0), gv1 * (d3 + b1));
            }
        }
    }
}

// ---------------- l2norm + scale + transpose from fused qkv buffer ---------
__global__ void l2n_kernel(const float* __restrict__ qkv, int base,
                           const float* __restrict__ scale, float* __restrict__ out)
{
    const int r    = blockIdx.x * 8 + (threadIdx.x >> 5);
    const int lane = threadIdx.x & 31;
    const int b = r / (Hh * Sq);
    const int h = (r / Sq) % Hh;
    const int s = r % Sq;
    const float* src = qkv + (size_t)(b * Sq + s) * (3*Dm) + base + h * DHd;
    float v0 = src[lane], v1 = src[lane + 32];
    float ss = v0 * v0 + v1 * v1;
    #pragma unroll
    for (int o = 16; o; o >>= 1) ss += __shfl_xor_sync(0xffffffffu, ss, o);
    const float inv = rsqrtf(ss + 1e-12f);
    float* dst = out + (size_t)r * DHd;
    dst[lane]      = v0 * inv * scale[h * DHd + lane];
    dst[lane + 32] = v1 * inv * scale[h * DHd + lane + 32];
}

__global__ void vtrans_kernel(const float* __restrict__ qkv, float* __restrict__ out)
{
    const int idx = blockIdx.x * 256 + threadIdx.x;
    const int d = idx & 63;
    const int s = (idx >> 6) & 1023;
    const int h = (idx >> 16) & 15;
    const int b = idx >> 20;
    out[idx] = qkv[(size_t)(b * Sq + s) * (3*Dm) + 2*Dm + h * DHd + d];
}

// ---------------- QK^T lower-triangle tiles ----------------
__global__ void __launch_bounds__(256)
qk_kernel(const float* __restrict__ qn, const float* __restrict__ kn,
          float* __restrict__ logits)
{
    const int jt = blockIdx.x, it = blockIdx.y, bh = blockIdx.z;
    if (jt > it) return;
    __shared__ float qs[64][65];
    __shared__ float ks[64][65];
    const float* qb = qn + ((size_t)bh * Sq + it * 64) * DHd;
    const float* kb = kn + ((size_t)bh * Sq + jt * 64) * DHd;
    const int tid = threadIdx.x;
    #pragma unroll
    for (int t = 0; t < 4; t++) {
        const int slot = tid + t * 256;
        const int r = slot >> 4, c4 = (slot & 15) << 2;
        float4 qv = *(const float4*)(qb + r * DHd + c4);
        qs[r][c4] = qv.x; qs[r][c4+1] = qv.y; qs[r][c4+2] = qv.z; qs[r][c4+3] = qv.w;
        float4 kv = *(const float4*)(kb + r * DHd + c4);
        ks[r][c4] = kv.x; ks[r][c4+1] = kv.y; ks[r][c4+2] = kv.z; ks[r][c4+3] = kv.w;
    }
    __syncthreads();
    const int ty = (tid >> 4) << 2;
    const int tx = (tid & 15) << 2;
    float acc[4][4] = {};
    #pragma unroll 16
    for (int k = 0; k < 64; k++) {
        float a0 = qs[ty][k], a1 = qs[ty+1][k], a2 = qs[ty+2][k], a3 = qs[ty+3][k];
        float b0 = ks[tx][k], b1 = ks[tx+1][k], b2 = ks[tx+2][k], b3 = ks[tx+3][k];
        acc[0][0] = fmaf(a0,b0,acc[0][0]); acc[0][1] = fmaf(a0,b1,acc[0][1]);
        acc[0][2] = fmaf(a0,b2,acc[0][2]); acc[0][3] = fmaf(a0,b3,acc[0][3]);
        acc[1][0] = fmaf(a1,b0,acc[1][0]); acc[1][1] = fmaf(a1,b1,acc[1][1]);
        acc[1][2] = fmaf(a1,b2,acc[1][2]); acc[1][3] = fmaf(a1,b3,acc[1][3]);
        acc[2][0] = fmaf(a2,b0,acc[2][0]); acc[2][1] = fmaf(a2,b1,acc[2][1]);
        acc[2][2] = fmaf(a2,b2,acc[2][2]); acc[2][3] = fmaf(a2,b3,acc[2][3]);
        acc[3][0] = fmaf(a3,b0,acc[3][0]); acc[3][1] = fmaf(a3,b1,acc[3][1]);
        acc[3][2] = fmaf(a3,b2,acc[3][2]); acc[3][3] = fmaf(a3,b3,acc[3][3]);
    }
    #pragma unroll
    for (int i = 0; i < 4; i++) {
        const size_t base = ((size_t)bh * Sq + it * 64 + ty + i) * Sq + jt * 64 + tx;
        #pragma unroll
        for (int j = 0; j < 4; j++)
            logits[base + j] = acc[i][j] * QK_SCALE;
    }
}

// ---------------- causal softmax in place ----------------
__global__ void softmax_kernel(float* __restrict__ l)
{
    const int row = blockIdx.x;
    const int i   = row & (Sq - 1);
    const int n   = i + 1;
    float* p = l + (size_t)row * Sq;
    __shared__ float red[128];
    const int tid = threadIdx.x;
    float m = -1e30f;
    for (int j = tid; j < n; j += 128) m = fmaxf(m, p[j]);
    red[tid] = m; __syncthreads();
    for (int off = 64; off > 0; off >>= 1) { if (tid < off) red[tid] = fmaxf(red[tid], red[tid+off]); __syncthreads(); }
    m = red[0]; __syncthreads();
    float s = 0.f;
    for (int j = tid; j < n; j += 128) s += expf(p[j] - m);
    red[tid] = s; __syncthreads();
    for (int off = 64; off > 0; off >>= 1) { if (tid < off) red[tid] += red[tid+off]; __syncthreads(); }
    const float inv = 1.0f / red[0];
    for (int j = tid; j < Sq; j += 128)
        p[j] = (j < n) ? expf(p[j] - m) * inv : 0.f;
}

// ---------------- P@V, writes attention out as bf16 hi/lo ----------------
__global__ void __launch_bounds__(256)
pv_kernel(const float* __restrict__ attn, const float* __restrict__ vn,
          __nv_bfloat16* __restrict__ aohi, __nv_bfloat16* __restrict__ aolo)
{
    const int it = blockIdx.x;
    const int bh = blockIdx.y;
    const int b = bh >> 4, h = bh & 15;
    __shared__ float as_[64][65];
    __shared__ float vs[64][65];
    const int tid = threadIdx.x;
    const int ty = (tid >> 4) << 2;
    const int tx = (tid & 15) << 2;
    float acc[4][4] = {};
    for (int kt = 0; kt <= it; kt++) {
        const float* ab = attn + ((size_t)bh * Sq + it * 64) * Sq + kt * 64;
        const float* vb = vn   + ((size_t)bh * Sq + kt * 64) * DHd;
        #pragma unroll
        for (int t = 0; t < 4; t++) {
            const int slot = tid + t * 256;
            const int r = slot >> 4, c4 = (slot & 15) << 2;
            float4 av = *(const float4*)(ab + (size_t)r * Sq + c4);
            as_[r][c4] = av.x; as_[r][c4+1] = av.y; as_[r][c4+2] = av.z; as_[r][c4+3] = av.w;
            float4 vv = *(const float4*)(vb + r * DHd + c4);
            vs[r][c4] = vv.x; vs[r][c4+1] = vv.y; vs[r][c4+2] = vv.z; vs[r][c4+3] = vv.w;
        }
        __syncthreads();
        #pragma unroll 16
        for (int k = 0; k < 64; k++) {
            float a0 = as_[ty][k], a1 = as_[ty+1][k], a2 = as_[ty+2][k], a3 = as_[ty+3][k];
            float b0 = vs[k][tx], b1 = vs[k][tx+1], b2 = vs[k][tx+2], b3 = vs[k][tx+3];
            acc[0][0] = fmaf(a0,b0,acc[0][0]); acc[0][1] = fmaf(a0,b1,acc[0][1]);
            acc[0][2] = fmaf(a0,b2,acc[0][2]); acc[0][3] = fmaf(a0,b3,acc[0][3]);
            acc[1][0] = fmaf(a1,b0,acc[1][0]); acc[1][1] = fmaf(a1,b1,acc[1][1]);
            acc[1][2] = fmaf(a1,b2,acc[1][2]); acc[1][3] = fmaf(a1,b3,acc[1][3]);
            acc[2][0] = fmaf(a2,b0,acc[2][0]); acc[2][1] = fmaf(a2,b1,acc[2][1]);
            acc[2][2] = fmaf(a2,b2,acc[2][2]); acc[2][3] = fmaf(a2,b3,acc[2][3]);
            acc[3][0] = fmaf(a3,b0,acc[3][0]); acc[3][1] = fmaf(a3,b1,acc[3][1]);
            acc[3][2] = fmaf(a3,b2,acc[3][2]); acc[3][3] = fmaf(a3,b3,acc[3][3]);
        }
        __syncthreads();
    }
    #pragma unroll
    for (int i = 0; i < 4; i++) {
        const size_t base = ((size_t)(b * Sq + it * 64 + ty + i)) * Dm + h * DHd + tx;
        #pragma unroll
        for (int j = 0; j < 4; j++) {
            float v = acc[i][j];
            __nv_bfloat16 hh = __float2bfloat16(v);
            aohi[base + j] = hh;
            aolo[base + j] = __float2bfloat16(v - __bfloat162float(hh));
        }
    }
}

// ---------------- gate: softmax(h2 @ gate_w + gate_b) over E=8 -------------
__global__ void gate_kernel(const float* __restrict__ h2, const float* __restrict__ gw,
                            const float* __restrict__ gb, float* __restrict__ gate)
{
    const int row = blockIdx.x;
    const int tid = threadIdx.x;
    const int e = tid >> 5, lane = tid & 31;
    const float* hr = h2 + (size_t)row * Dm;
    float s = 0.f;
    for (int k = lane; k < Dm; k += 32) s += hr[k] * gw[k * Ex + e];
    #pragma unroll
    for (int o = 16; o; o >>= 1) s += __shfl_xor_sync(0xffffffffu, s, o);
    __shared__ float lg[Ex];
    if (lane == 0) lg[e] = s + gb[e];
    __syncthreads();
    if (tid == 0) {
        float m = lg[0];
        #pragma unroll
        for (int q = 1; q < Ex; q++) m = fmaxf(m, lg[q]);
        float ex[Ex], sum = 0.f;
        #pragma unroll
        for (int q = 0; q < Ex; q++) { ex[q] = expf(lg[q] - m); sum += ex[q]; }
        const float inv = 1.0f / sum;
        #pragma unroll
        for (int q = 0; q < Ex; q++) gate[(size_t)row * Ex + q] = ex[q] * inv;
    }
}

// ---------------- sum 8 expert outputs + final LayerNorm -------------------
__global__ void redln_kernel(const float* __restrict__ expout, const float* __restrict__ g,
                             const float* __restrict__ b, float* __restrict__ out)
{
    __shared__ float buf[Dm];
    __shared__ float red[256];
    const int row = blockIdx.x;
    const int tid = threadIdx.x;
    float s = 0.f;
    for (int i = tid; i < Dm; i += 256) {
        float v = 0.f;
        #pragma unroll
        for (int e = 0; e < Ex; e++)
            v += expout[(size_t)e * ROWS * Dm + (size_t)row * Dm + i];
        buf[i] = v; s += v;
    }
    red[tid] = s; __syncthreads();
    for (int off = 128; off > 0; off >>= 1) { if (tid < off) red[tid] += red[tid+off]; __syncthreads(); }
    const float mean = red[0] * (1.0f / Dm);
    __syncthreads();
    float s2 = 0.f;
    for (int i = tid; i < Dm; i += 256) { float d = buf[i] - mean; s2 += d * d; }
    red[tid] = s2; __syncthreads();
    for (int off = 128; off > 0; off >>= 1) { if (tid < off) red[tid] += red[tid+off]; __syncthreads(); }
    const float inv = rsqrtf(red[0] * (1.0f / Dm) + 1e-5f);
    for (int i = tid; i < Dm; i += 256)
        out[(size_t)row * Dm + i] = (buf[i] - mean) * inv * g[i] + b[i];
}

// ---------------- launch ----------------
extern "C" void kernel_launch(void* const* d_in, const int* in_sizes, int n_in,
                              void* d_out, int out_size)
{
    const float* x       = (const float*)d_in[0];
    const float* ln_g    = (const float*)d_in[1];
    const float* ln_b    = (const float*)d_in[2];
    const float* Wq      = (const float*)d_in[3];
    const float* Wk      = (const float*)d_in[4];
    const float* Wv      = (const float*)d_in[5];
    const float* q_scale = (const float*)d_in[6];
    const float* k_scale = (const float*)d_in[7];
    const float* Wo      = (const float*)d_in[8];
    const float* gate_w  = (const float*)d_in[9];
    const float* gate_b  = (const float*)d_in[10];
    const float* w1      = (const float*)d_in[11];
    const float* b1      = (const float*)d_in[12];
    const float* w2      = (const float*)d_in[13];
    const float* b2      = (const float*)d_in[14];
    float* out = (float*)d_out;

    __nv_bfloat16 *h1hi, *h1lo, *aohi, *aolo, *h2hi, *h2lo, *hidhi, *hidlo;
    __nv_bfloat16 *wqkvThi, *wqkvTlo, *woThi, *woTlo, *w1Thi, *w1Tlo, *w2Thi, *w2Tlo;
    float *qkvf, *qn, *kn, *vn, *logits, *o, *h2, *gate, *expout;
    cudaGetSymbolAddress((void**)&h1hi, g_h1hi);   cudaGetSymbolAddress((void**)&h1lo, g_h1lo);
    cudaGetSymbolAddress((void**)&qkvf, g_qkvf);
    cudaGetSymbolAddress((void**)&qn, g_qn);       cudaGetSymbolAddress((void**)&kn, g_kn);
    cudaGetSymbolAddress((void**)&vn, g_vn);       cudaGetSymbolAddress((void**)&logits, g_logits);
    cudaGetSymbolAddress((void**)&aohi, g_aohi);   cudaGetSymbolAddress((void**)&aolo, g_aolo);
    cudaGetSymbolAddress((void**)&o, g_o);         cudaGetSymbolAddress((void**)&h2, g_h2);
    cudaGetSymbolAddress((void**)&h2hi, g_h2hi);   cudaGetSymbolAddress((void**)&h2lo, g_h2lo);
    cudaGetSymbolAddress((void**)&gate, g_gate);
    cudaGetSymbolAddress((void**)&hidhi, g_hidhi); cudaGetSymbolAddress((void**)&hidlo, g_hidlo);
    cudaGetSymbolAddress((void**)&expout, g_expout);
    cudaGetSymbolAddress((void**)&wqkvThi, g_wqkvThi); cudaGetSymbolAddress((void**)&wqkvTlo, g_wqkvTlo);
    cudaGetSymbolAddress((void**)&woThi, g_woThi);     cudaGetSymbolAddress((void**)&woTlo, g_woTlo);
    cudaGetSymbolAddress((void**)&w1Thi, g_w1Thi);     cudaGetSymbolAddress((void**)&w1Tlo, g_w1Tlo);
    cudaGetSymbolAddress((void**)&w2Thi, g_w2Thi);     cudaGetSymbolAddress((void**)&w2Tlo, g_w2Tlo);

    cudaFuncSetAttribute(bgemm_kernel<0>, cudaFuncAttributeMaxDynamicSharedMemorySize, SMEM_TOTAL_G);
    cudaFuncSetAttribute(bgemm_kernel<1>, cudaFuncAttributeMaxDynamicSharedMemorySize, SMEM_TOTAL_G);
    cudaFuncSetAttribute(bgemm_kernel<2>, cudaFuncAttributeMaxDynamicSharedMemorySize, SMEM_TOTAL_G);

    // 0. weight prep: transpose + bf16 hi/lo split
    wprep_kernel<<<dim3(Dm/32, Dm/32, 1), dim3(32,8)>>>(Wq, wqkvThi,           wqkvTlo,           Dm, Dm);
    wprep_kernel<<<dim3(Dm/32, Dm/32, 1), dim3(32,8)>>>(Wk, wqkvThi + Dm*Dm,   wqkvTlo + Dm*Dm,   Dm, Dm);
    wprep_kernel<<<dim3(Dm/32, Dm/32, 1), dim3(32,8)>>>(Wv, wqkvThi + 2*Dm*Dm, wqkvTlo + 2*Dm*Dm, Dm, Dm);
    wprep_kernel<<<dim3(Dm/32, Dm/32, 1), dim3(32,8)>>>(Wo, woThi, woTlo, Dm, Dm);
    wprep_kernel<<<dim3(FFd/32, Dm/32, Ex), dim3(32,8)>>>(w1, w1Thi, w1Tlo, Dm, FFd);
    wprep_kernel<<<dim3(Dm/32, FFd/32, Ex), dim3(32,8)>>>(w2, w2Thi, w2Tlo, FFd, Dm);

    // 1. pre-attention LN -> bf16 hi/lo
    ln_kernel<<<ROWS, 256>>>(x, ln_g, ln_b, nullptr, h1hi, h1lo);

    // 2. fused QKV projection: [2048,1024] @ [1024,3072]^T(prepped) -> qkvf
    bgemm_kernel<0><<<dim3(3*Dm/BN, ROWS/BM, 1), 256, SMEM_TOTAL_G>>>(
        h1hi, h1lo, wqkvThi, wqkvTlo, 3*Dm, Dm, 0, 0, 0,
        qkvf, nullptr, nullptr, nullptr, 0, nullptr);

    // 3. l2norm+scale+transpose q,k; transpose v
    l2n_kernel<<<(BH*Sq)/8, 256>>>(qkvf, 0,    q_scale, qn);
    l2n_kernel<<<(BH*Sq)/8, 256>>>(qkvf, Dm,   k_scale, kn);
    vtrans_kernel<<<(BH*Sq*DHd)/256, 256>>>(qkvf, vn);

    // 4. attention (fp32)
    qk_kernel<<<dim3(Sq/64, Sq/64, BH), 256>>>(qn, kn, logits);
    softmax_kernel<<<BH*Sq, 128>>>(logits);
    pv_kernel<<<dim3(Sq/64, BH), 256>>>(logits, vn, aohi, aolo);

    // 5. output projection + mid LN
    bgemm_kernel<0><<<dim3(Dm/BN, ROWS/BM, 1), 256, SMEM_TOTAL_G>>>(
        aohi, aolo, woThi, woTlo, Dm, Dm, 0, 0, 0,
        o, nullptr, nullptr, nullptr, 0, nullptr);
    ln_kernel<<<ROWS, 256>>>(o, ln_g, ln_b, h2, h2hi, h2lo);

    // 6. gate
    gate_kernel<<<ROWS, 256>>>(h2, gate_w, gate_b, gate);

    // 7. MoE GEMM1 (all experts batched): gelu(h2 @ w1 + b1) -> hid hi/lo
    bgemm_kernel<1><<<dim3(FFd/BN, ROWS/BM, Ex), 256, SMEM_TOTAL_G>>>(
        h2hi, h2lo, w1Thi, w1Tlo, FFd, Dm,
        0, (long long)FFd*Dm, (long long)ROWS*FFd,
        nullptr, hidhi, hidlo, b1, FFd, nullptr);

    // 8. MoE GEMM2: gate*(hid @ w2 + b2) -> per-expert expout
    bgemm_kernel<2><<<dim3(Dm/BN, ROWS/BM, Ex), 256, SMEM_TOTAL_G>>>(
        hidhi, hidlo, w2Thi, w2Tlo, Dm, FFd,
        (long long)ROWS*FFd, (long long)Dm*FFd, (long long)ROWS*Dm,
        expout, nullptr, nullptr, b2, Dm, gate);

    // 9. sum experts + final LN -> out
    redln_kernel<<<ROWS, 256>>>(expout, ln_g, ln_b, out);
}

// round 4
// speedup vs baseline: 3.7724x; 1.0573x over previous
#include <cuda_runtime.h>
#include <cuda_bf16.h>
#include <math.h>
#include <stdint.h>

// ---------------- problem constants ----------------
#define Bc   2
#define Sq   1024
#define Dm   1024
#define Hh   16
#define DHd  64
#define Ex   8
#define FFd  4096
#define BH   (Bc*Hh)     // 32
#define ROWS (Bc*Sq)     // 2048
#define QK_SCALE 10.0f

// GEMM tiling
#define BM 128
#define BN 128
#define BK 64
#define LDS 72                      // BK + 8 pad (bf16 units)
#define MAT_BYTES (128*LDS*2)       // 18432 bytes per 128x64 tile
#define MATB64 (64*LDS*2)           // 9216 bytes per 64x64 tile
#define STAGE_BYTES (4*MAT_BYTES)   // Ahi,Alo,Bhi,Blo
#define SMEM_TOTAL_G (2*STAGE_BYTES) // 147456
#define SMEM_QK (4*MAT_BYTES)        // 73728 single stage
#define PV_STAGE (2*MAT_BYTES + 2*MATB64)  // 55296
#define SMEM_PV (2*PV_STAGE)         // 110592

// ---------------- low-level helpers ----------------
__device__ __forceinline__ uint32_t smem_u32(const void* p) {
    uint32_t a;
    asm("{ .reg .u64 t; cvta.to.shared.u64 t, %1; cvt.u32.u64 %0, t; }" : "=r"(a) : "l"(p));
    return a;
}
__device__ __forceinline__ void cp16(uint32_t dst, const void* src) {
    asm volatile("cp.async.cg.shared.global [%0], [%1], 16;" :: "r"(dst), "l"(src));
}
#define CP_COMMIT() asm volatile("cp.async.commit_group;" ::: "memory")
#define CP_WAIT(n)  asm volatile("cp.async.wait_group %0;" :: "n"(n) : "memory")

#define LDSM_X4(r0, r1, r2, r3, addr) \
    asm volatile("ldmatrix.sync.aligned.m8n8.x4.shared.b16 {%0,%1,%2,%3}, [%4];" \
        : "=r"(r0), "=r"(r1), "=r"(r2), "=r"(r3) : "r"(addr))

#define MMA_BF16(d, a, b0, b1) \
    asm volatile("mma.sync.aligned.m16n8k16.row.col.f32.bf16.bf16.f32 " \
        "{%0,%1,%2,%3}, {%4,%5,%6,%7}, {%8,%9}, {%0,%1,%2,%3};" \
        : "+f"((d)[0]), "+f"((d)[1]), "+f"((d)[2]), "+f"((d)[3]) \
        : "r"((a)[0]), "r"((a)[1]), "r"((a)[2]), "r"((a)[3]), "r"(b0), "r"(b1))

// ---------------- scratch (device globals) ----------------
__device__ __nv_bfloat16 g_h1hi[ROWS*Dm], g_h1lo[ROWS*Dm];
__device__ float g_qkvf[ROWS*3*Dm];
__device__ __nv_bfloat16 g_qnh[BH*Sq*DHd], g_qnl[BH*Sq*DHd];
__device__ __nv_bfloat16 g_knh[BH*Sq*DHd], g_knl[BH*Sq*DHd];
__device__ __nv_bfloat16 g_vTh[BH*DHd*Sq], g_vTl[BH*DHd*Sq];
__device__ float g_logits[(size_t)BH*Sq*Sq];
__device__ __nv_bfloat16 g_Phi[(size_t)BH*Sq*Sq], g_Plo[(size_t)BH*Sq*Sq];
__device__ __nv_bfloat16 g_aohi[ROWS*Dm], g_aolo[ROWS*Dm];
__device__ float g_o[ROWS*Dm], g_h2[ROWS*Dm];
__device__ __nv_bfloat16 g_h2hi[ROWS*Dm], g_h2lo[ROWS*Dm];
__device__ float g_gate[ROWS*Ex];
__device__ __nv_bfloat16 g_hidhi[(size_t)Ex*ROWS*FFd], g_hidlo[(size_t)Ex*ROWS*FFd];
__device__ float g_expout[(size_t)Ex*ROWS*Dm];
__device__ __nv_bfloat16 g_wqkvThi[3*Dm*Dm], g_wqkvTlo[3*Dm*Dm];
__device__ __nv_bfloat16 g_woThi[Dm*Dm], g_woTlo[Dm*Dm];
__device__ __nv_bfloat16 g_w1Thi[(size_t)Ex*FFd*Dm], g_w1Tlo[(size_t)Ex*FFd*Dm];
__device__ __nv_bfloat16 g_w2Thi[(size_t)Ex*Dm*FFd], g_w2Tlo[(size_t)Ex*Dm*FFd];

// ---------------- math helpers ----------------
__device__ __forceinline__ float gelu_f(float x) {
    float x3 = x * x * x;
    float t  = tanhf(0.7978845608028654f * (x + 0.044715f * x3));
    return 0.5f * x * (1.0f + t);
}

// ---------------- weight transpose + bf16 split: W[K,N] -> hi/lo [N,K] ------
__global__ void wprep_kernel(const float* __restrict__ W, __nv_bfloat16* __restrict__ hi,
                             __nv_bfloat16* __restrict__ lo, int K, int N)
{
    __shared__ float t[32][33];
    const size_t zoff = (size_t)blockIdx.z * K * N;
    const int k0 = blockIdx.y * 32, n0 = blockIdx.x * 32;
    const int tx = threadIdx.x, ty = threadIdx.y; // 32 x 8
    #pragma unroll
    for (int i = 0; i < 4; i++)
        t[ty + 8*i][tx] = W[zoff + (size_t)(k0 + ty + 8*i) * N + n0 + tx];
    __syncthreads();
    #pragma unroll
    for (int i = 0; i < 4; i++) {
        float v = t[tx][ty + 8*i];
        const size_t o = zoff + (size_t)(n0 + ty + 8*i) * K + k0 + tx;
        __nv_bfloat16 h = __float2bfloat16(v);
        hi[o] = h;
        lo[o] = __float2bfloat16(v - __bfloat162float(h));
    }
}

// ---------------- LayerNorm (optional fp32 + hi/lo outputs) ----------------
__global__ void ln_kernel(const float* __restrict__ x, const float* __restrict__ g,
                          const float* __restrict__ b, float* __restrict__ yf,
                          __nv_bfloat16* __restrict__ yhi, __nv_bfloat16* __restrict__ ylo)
{
    __shared__ float buf[Dm];
    __shared__ float red[256];
    const int row = blockIdx.x;
    const int tid = threadIdx.x;
    const float* xr = x + (size_t)row * Dm;
    float s = 0.f;
    for (int i = tid; i < Dm; i += 256) { float v = xr[i]; buf[i] = v; s += v; }
    red[tid] = s; __syncthreads();
    for (int off = 128; off > 0; off >>= 1) { if (tid < off) red[tid] += red[tid+off]; __syncthreads(); }
    const float mean = red[0] * (1.0f / Dm);
    __syncthreads();
    float s2 = 0.f;
    for (int i = tid; i < Dm; i += 256) { float d = buf[i] - mean; s2 += d * d; }
    red[tid] = s2; __syncthreads();
    for (int off = 128; off > 0; off >>= 1) { if (tid < off) red[tid] += red[tid+off]; __syncthreads(); }
    const float inv = rsqrtf(red[0] * (1.0f / Dm) + 1e-5f);
    for (int i = tid; i < Dm; i += 256) {
        float v = (buf[i] - mean) * inv * g[i] + b[i];
        if (yf) yf[(size_t)row*Dm + i] = v;
        if (yhi) {
            __nv_bfloat16 h = __float2bfloat16(v);
            yhi[(size_t)row*Dm + i] = h;
            ylo[(size_t)row*Dm + i] = __float2bfloat16(v - __bfloat162float(h));
        }
    }
}

// ---------------- mma.sync bf16x3 GEMM: D[M,N] = A[M,K] @ B[N,K]^T ----------
// EPI 0: fp32 store; EPI 1: gelu(acc+bias) -> bf16 hi/lo; EPI 2: gate*(acc+bias) -> fp32
template<int EPI>
__global__ void __launch_bounds__(256, 1)
bgemm_kernel(const __nv_bfloat16* __restrict__ Ahi, const __nv_bfloat16* __restrict__ Alo,
             const __nv_bfloat16* __restrict__ Bhi, const __nv_bfloat16* __restrict__ Blo,
             int N, int K,
             long long az, long long bz, long long oz,
             float* __restrict__ outf,
             __nv_bfloat16* __restrict__ outhi, __nv_bfloat16* __restrict__ outlo,
             const float* __restrict__ bias, long long biasz,
             const float* __restrict__ gate)
{
    extern __shared__ char smem[];
    const uint32_t sbase = smem_u32(smem);
    const int tid  = threadIdx.x;
    const int wid  = tid >> 5;
    const int lane = tid & 31;
    const int wm   = wid >> 1;       // 0..3
    const int wn   = wid & 1;        // 0..1
    const int m0 = blockIdx.y * BM;
    const int n0 = blockIdx.x * BN;
    const int e  = blockIdx.z;

    const __nv_bfloat16* pAhi = Ahi + (size_t)e * az;
    const __nv_bfloat16* pAlo = Alo + (size_t)e * az;
    const __nv_bfloat16* pBhi = Bhi + (size_t)e * bz;
    const __nv_bfloat16* pBlo = Blo + (size_t)e * bz;

    const int lrow = tid >> 3;            // 0..31
    const int lc8  = (tid & 7) * 8;       // bf16 col offset

    float acc[2][8][4];
    #pragma unroll
    for (int i = 0; i < 2; i++)
        #pragma unroll
        for (int j = 0; j < 8; j++)
            #pragma unroll
            for (int q = 0; q < 4; q++) acc[i][j][q] = 0.f;

    const int NB = K / BK;

    // prefetch stage 0
    {
        const uint32_t so = sbase;
        #pragma unroll
        for (int i = 0; i < 4; i++) {
            const int row = lrow + i * 32;
            const uint32_t sa = so + (uint32_t)(row * LDS + lc8) * 2;
            const size_t ga = (size_t)(m0 + row) * K + lc8;
            const size_t gb = (size_t)(n0 + row) * K + lc8;
            cp16(sa,                 pAhi + ga);
            cp16(sa + MAT_BYTES,     pAlo + ga);
            cp16(sa + 2*MAT_BYTES,   pBhi + gb);
            cp16(sa + 3*MAT_BYTES,   pBlo + gb);
        }
        CP_COMMIT();
    }

    uint32_t ah[2][2][4], al[2][2][4], bhf[2][4][4], blf[2][4][4];

    for (int kb = 0; kb < NB; kb++) {
        const int s = kb & 1;
        if (kb + 1 < NB) {
            const int kk = (kb + 1) * BK;
            const uint32_t so = sbase + (s ^ 1) * STAGE_BYTES;
            #pragma unroll
            for (int i = 0; i < 4; i++) {
                const int row = lrow + i * 32;
                const uint32_t sa = so + (uint32_t)(row * LDS + lc8) * 2;
                const size_t ga = (size_t)(m0 + row) * K + kk + lc8;
                const size_t gb = (size_t)(n0 + row) * K + kk + lc8;
                cp16(sa,                 pAhi + ga);
                cp16(sa + MAT_BYTES,     pAlo + ga);
                cp16(sa + 2*MAT_BYTES,   pBhi + gb);
                cp16(sa + 3*MAT_BYTES,   pBlo + gb);
            }
            CP_COMMIT();
            CP_WAIT(1);
        } else {
            CP_WAIT(0);
        }
        __syncthreads();

        const uint32_t so = sbase + s * STAGE_BYTES;

        auto load_frags = [&](int k16, int bsel) {
            const int kc = k16 * 16;
            #pragma unroll
            for (int mt = 0; mt < 2; mt++) {
                const int arow = wm * 32 + mt * 16 + (lane & 15);
                const int acol = kc + ((lane >> 4) << 3);
                const uint32_t addr = so + (uint32_t)(arow * LDS + acol) * 2;
                LDSM_X4(ah[bsel][mt][0], ah[bsel][mt][1], ah[bsel][mt][2], ah[bsel][mt][3], addr);
                LDSM_X4(al[bsel][mt][0], al[bsel][mt][1], al[bsel][mt][2], al[bsel][mt][3], addr + MAT_BYTES);
            }
            #pragma unroll
            for (int p = 0; p < 4; p++) {
                const int nrow = wn * 64 + p * 16 + (lane & 7) + ((lane & 16) >> 1);
                const int ncol = kc + (lane & 8);
                const uint32_t addr = so + 2*MAT_BYTES + (uint32_t)(nrow * LDS + ncol) * 2;
                LDSM_X4(bhf[bsel][p][0], bhf[bsel][p][1], bhf[bsel][p][2], bhf[bsel][p][3], addr);
                LDSM_X4(blf[bsel][p][0], blf[bsel][p][1], blf[bsel][p][2], blf[bsel][p][3], addr + MAT_BYTES);
            }
        };

        load_frags(0, 0);
        #pragma unroll
        for (int k16 = 0; k16 < 4; k16++) {
            const int cur = k16 & 1;
            if (k16 < 3) load_frags(k16 + 1, cur ^ 1);
            #pragma unroll
            for (int mt = 0; mt < 2; mt++) {
                #pragma unroll
                for (int nt = 0; nt < 8; nt++) {
                    const int pr = nt >> 1, ix = (nt & 1) * 2;
                    MMA_BF16(acc[mt][nt], ah[cur][mt], bhf[cur][pr][ix], bhf[cur][pr][ix+1]);
                    MMA_BF16(acc[mt][nt], al[cur][mt], bhf[cur][pr][ix], bhf[cur][pr][ix+1]);
                    MMA_BF16(acc[mt][nt], ah[cur][mt], blf[cur][pr][ix], blf[cur][pr][ix+1]);
                }
            }
        }
        __syncthreads();
    }

    // epilogue
    #pragma unroll
    for (int mt = 0; mt < 2; mt++) {
        const int rA = m0 + wm * 32 + mt * 16 + (lane >> 2);
        const int rB = rA + 8;
        float gv0 = 0.f, gv1 = 0.f;
        if (EPI == 2) {
            gv0 = gate[(size_t)rA * Ex + e];
            gv1 = gate[(size_t)rB * Ex + e];
        }
        #pragma unroll
        for (int nt = 0; nt < 8; nt++) {
            const int col = n0 + wn * 64 + nt * 8 + (lane & 3) * 2;
            float d0 = acc[mt][nt][0], d1 = acc[mt][nt][1];
            float d2 = acc[mt][nt][2], d3 = acc[mt][nt][3];
            if (EPI == 0) {
                *(float2*)(outf + (size_t)rA * N + col) = make_float2(d0, d1);
                *(float2*)(outf + (size_t)rB * N + col) = make_float2(d2, d3);
            } else if (EPI == 1) {
                const float b0 = bias[(size_t)e * biasz + col];
                const float b1 = bias[(size_t)e * biasz + col + 1];
                float v0 = gelu_f(d0 + b0), v1 = gelu_f(d1 + b1);
                float v2 = gelu_f(d2 + b0), v3 = gelu_f(d3 + b1);
                __nv_bfloat16 h0 = __float2bfloat16(v0), h1 = __float2bfloat16(v1);
                __nv_bfloat16 h2 = __float2bfloat16(v2), h3 = __float2bfloat16(v3);
                __nv_bfloat162 hhA; hhA.x = h0; hhA.y = h1;
                __nv_bfloat162 hhB; hhB.x = h2; hhB.y = h3;
                __nv_bfloat162 llA, llB;
                llA.x = __float2bfloat16(v0 - __bfloat162float(h0));
                llA.y = __float2bfloat16(v1 - __bfloat162float(h1));
                llB.x = __float2bfloat16(v2 - __bfloat162float(h2));
                llB.y = __float2bfloat16(v3 - __bfloat162float(h3));
                const size_t gA = (size_t)e * oz + (size_t)rA * N + col;
                const size_t gB = (size_t)e * oz + (size_t)rB * N + col;
                *(__nv_bfloat162*)(outhi + gA) = hhA;
                *(__nv_bfloat162*)(outlo + gA) = llA;
                *(__nv_bfloat162*)(outhi + gB) = hhB;
                *(__nv_bfloat162*)(outlo + gB) = llB;
            } else {
                const float b0 = bias[(size_t)e * biasz + col];
                const float b1 = bias[(size_t)e * biasz + col + 1];
                const size_t gA = (size_t)e * oz + (size_t)rA * N + col;
                const size_t gB = (size_t)e * oz + (size_t)rB * N + col;
                *(float2*)(outf + gA) = make_float2(gv0 * (d0 + b0), gv0 * (d1 + b1));
                *(float2*)(outf + gB) = make_float2(gv1 * (d2 + b0), gv1 * (d3 + b1));
            }
        }
    }
}

// ---------------- l2norm + scale -> bf16 hi/lo [bh, s, 64] -----------------
__global__ void l2n_kernel(const float* __restrict__ qkv, int base,
                           const float* __restrict__ scale,
                           __nv_bfloat16* __restrict__ oh, __nv_bfloat16* __restrict__ ol)
{
    const int r    = blockIdx.x * 8 + (threadIdx.x >> 5);
    const int lane = threadIdx.x & 31;
    const int b = r / (Hh * Sq);
    const int h = (r / Sq) % Hh;
    const int s = r % Sq;
    const float* src = qkv + (size_t)(b * Sq + s) * (3*Dm) + base + h * DHd;
    float v0 = src[lane], v1 = src[lane + 32];
    float ss = v0 * v0 + v1 * v1;
    #pragma unroll
    for (int o = 16; o; o >>= 1) ss += __shfl_xor_sync(0xffffffffu, ss, o);
    const float inv = rsqrtf(ss + 1e-12f);
    float f0 = v0 * inv * scale[h * DHd + lane];
    float f1 = v1 * inv * scale[h * DHd + lane + 32];
    const size_t d = (size_t)r * DHd;
    __nv_bfloat16 h0 = __float2bfloat16(f0);
    __nv_bfloat16 h1 = __float2bfloat16(f1);
    oh[d + lane]      = h0;
    ol[d + lane]      = __float2bfloat16(f0 - __bfloat162float(h0));
    oh[d + lane + 32] = h1;
    ol[d + lane + 32] = __float2bfloat16(f1 - __bfloat162float(h1));
}

// ---------------- V transpose -> vT hi/lo [bh, d, s] ----------------
__global__ void vtrans_kernel(const float* __restrict__ qkv,
                              __nv_bfloat16* __restrict__ vh, __nv_bfloat16* __restrict__ vl)
{
    __shared__ float t[32][33];
    const int bh = blockIdx.z;
    const int b = bh >> 4, h = bh & 15;
    const int s0 = blockIdx.x * 32, d0 = blockIdx.y * 32;
    const int tx = threadIdx.x, ty = threadIdx.y;  // 32 x 8
    #pragma unroll
    for (int i = 0; i < 4; i++)
        t[ty + 8*i][tx] = qkv[(size_t)(b * Sq + s0 + ty + 8*i) * (3*Dm) + 2*Dm + h * DHd + d0 + tx];
    __syncthreads();
    #pragma unroll
    for (int i = 0; i < 4; i++) {
        float v = t[tx][ty + 8*i];
        const size_t o = ((size_t)bh * DHd + d0 + ty + 8*i) * Sq + s0 + tx;
        __nv_bfloat16 hh = __float2bfloat16(v);
        vh[o] = hh;
        vl[o] = __float2bfloat16(v - __bfloat162float(hh));
    }
}

// ---------------- QK^T via mma (lower-triangle 128x128 tiles) ---------------
__global__ void __launch_bounds__(256, 1)
qk_mma_kernel(const __nv_bfloat16* __restrict__ qh, const __nv_bfloat16* __restrict__ ql,
              const __nv_bfloat16* __restrict__ kh, const __nv_bfloat16* __restrict__ kl,
              float* __restrict__ logits)
{
    extern __shared__ char smem[];
    const uint32_t sbase = smem_u32(smem);
    const int tid  = threadIdx.x;
    const int wid  = tid >> 5;
    const int lane = tid & 31;
    const int wm   = wid >> 1;
    const int wn   = wid & 1;
    const int bh   = blockIdx.y;
    int t = blockIdx.x;
    int it = 0;
    while ((it + 1) * (it + 2) / 2 <= t) it++;
    const int jt = t - it * (it + 1) / 2;

    const int lrow = tid >> 3;
    const int lc8  = (tid & 7) * 8;

    // load q tile (128x64) hi/lo and k tile hi/lo
    {
        #pragma unroll
        for (int i = 0; i < 4; i++) {
            const int row = lrow + i * 32;
            const uint32_t sa = sbase + (uint32_t)(row * LDS + lc8) * 2;
            const size_t gq = ((size_t)bh * Sq + it * 128 + row) * DHd + lc8;
            const size_t gk = ((size_t)bh * Sq + jt * 128 + row) * DHd + lc8;
            cp16(sa,                 qh + gq);
            cp16(sa + MAT_BYTES,     ql + gq);
            cp16(sa + 2*MAT_BYTES,   kh + gk);
            cp16(sa + 3*MAT_BYTES,   kl + gk);
        }
        CP_COMMIT();
        CP_WAIT(0);
        __syncthreads();
    }

    float acc[2][8][4];
    #pragma unroll
    for (int i = 0; i < 2; i++)
        #pragma unroll
        for (int j = 0; j < 8; j++)
            #pragma unroll
            for (int q = 0; q < 4; q++) acc[i][j][q] = 0.f;

    uint32_t ah[2][2][4], al[2][2][4], bhf[2][4][4], blf[2][4][4];
    auto load_frags = [&](int k16, int bsel) {
        const int kc = k16 * 16;
        #pragma unroll
        for (int mt = 0; mt < 2; mt++) {
            const int arow = wm * 32 + mt * 16 + (lane & 15);
            const int acol = kc + ((lane >> 4) << 3);
            const uint32_t addr = sbase + (uint32_t)(arow * LDS + acol) * 2;
            LDSM_X4(ah[bsel][mt][0], ah[bsel][mt][1], ah[bsel][mt][2], ah[bsel][mt][3], addr);
            LDSM_X4(al[bsel][mt][0], al[bsel][mt][1], al[bsel][mt][2], al[bsel][mt][3], addr + MAT_BYTES);
        }
        #pragma unroll
        for (int p = 0; p < 4; p++) {
            const int nrow = wn * 64 + p * 16 + (lane & 7) + ((lane & 16) >> 1);
            const int ncol = kc + (lane & 8);
            const uint32_t addr = sbase + 2*MAT_BYTES + (uint32_t)(nrow * LDS + ncol) * 2;
            LDSM_X4(bhf[bsel][p][0], bhf[bsel][p][1], bhf[bsel][p][2], bhf[bsel][p][3], addr);
            LDSM_X4(blf[bsel][p][0], blf[bsel][p][1], blf[bsel][p][2], blf[bsel][p][3], addr + MAT_BYTES);
        }
    };

    load_frags(0, 0);
    #pragma unroll
    for (int k16 = 0; k16 < 4; k16++) {
        const int cur = k16 & 1;
        if (k16 < 3) load_frags(k16 + 1, cur ^ 1);
        #pragma unroll
        for (int mt = 0; mt < 2; mt++) {
            #pragma unroll
            for (int nt = 0; nt < 8; nt++) {
                const int pr = nt >> 1, ix = (nt & 1) * 2;
                MMA_BF16(acc[mt][nt], ah[cur][mt], bhf[cur][pr][ix], bhf[cur][pr][ix+1]);
                MMA_BF16(acc[mt][nt], al[cur][mt], bhf[cur][pr][ix], bhf[cur][pr][ix+1]);
                MMA_BF16(acc[mt][nt], ah[cur][mt], blf[cur][pr][ix], blf[cur][pr][ix+1]);
            }
        }
    }

    // store logits * QK_SCALE (masked cols j>i are never read by softmax)
    #pragma unroll
    for (int mt = 0; mt < 2; mt++) {
        const size_t rA = (size_t)bh * Sq + it * 128 + wm * 32 + mt * 16 + (lane >> 2);
        const size_t rB = rA + 8;
        #pragma unroll
        for (int nt = 0; nt < 8; nt++) {
            const int col = jt * 128 + wn * 64 + nt * 8 + (lane & 3) * 2;
            *(float2*)(logits + rA * Sq + col) =
                make_float2(acc[mt][nt][0] * QK_SCALE, acc[mt][nt][1] * QK_SCALE);
            *(float2*)(logits + rB * Sq + col) =
                make_float2(acc[mt][nt][2] * QK_SCALE, acc[mt][nt][3] * QK_SCALE);
        }
    }
}

// ---------------- causal softmax: fp32 logits -> bf16 hi/lo P ---------------
__global__ void softmax_kernel(const float* __restrict__ l,
                               __nv_bfloat16* __restrict__ phi, __nv_bfloat16* __restrict__ plo)
{
    const int row = blockIdx.x;
    const int i   = row & (Sq - 1);
    const int n   = i + 1;
    const float* p = l + (size_t)row * Sq;
    __shared__ float red[128];
    const int tid = threadIdx.x;
    float m = -1e30f;
    for (int j = tid; j < n; j += 128) m = fmaxf(m, p[j]);
    red[tid] = m; __syncthreads();
    for (int off = 64; off > 0; off >>= 1) { if (tid < off) red[tid] = fmaxf(red[tid], red[tid+off]); __syncthreads(); }
    m = red[0]; __syncthreads();
    float s = 0.f;
    for (int j = tid; j < n; j += 128) s += expf(p[j] - m);
    red[tid] = s; __syncthreads();
    for (int off = 64; off > 0; off >>= 1) { if (tid < off) red[tid] += red[tid+off]; __syncthreads(); }
    const float inv = 1.0f / red[0];
    for (int j2 = tid; j2 < Sq / 2; j2 += 128) {
        const int j = j2 * 2;
        float v0 = (j     < n) ? expf(p[j]   - m) * inv : 0.f;
        float v1 = (j + 1 < n) ? expf(p[j+1] - m) * inv : 0.f;
        __nv_bfloat16 h0 = __float2bfloat16(v0);
        __nv_bfloat16 h1 = __float2bfloat16(v1);
        __nv_bfloat162 hh; hh.x = h0; hh.y = h1;
        __nv_bfloat162 ll;
        ll.x = __float2bfloat16(v0 - __bfloat162float(h0));
        ll.y = __float2bfloat16(v1 - __bfloat162float(h1));
        *(__nv_bfloat162*)(phi + (size_t)row * Sq + j) = hh;
        *(__nv_bfloat162*)(plo + (size_t)row * Sq + j) = ll;
    }
}

// ---------------- P@V via mma: [128q x 64d], K = (it+1)*128 -----------------
__global__ void __launch_bounds__(256, 1)
pv_mma_kernel(const __nv_bfloat16* __restrict__ ph, const __nv_bfloat16* __restrict__ pl,
              const __nv_bfloat16* __restrict__ vh, const __nv_bfloat16* __restrict__ vl,
              __nv_bfloat16* __restrict__ aohi, __nv_bfloat16* __restrict__ aolo)
{
    extern __shared__ char smem[];
    const uint32_t sbase = smem_u32(smem);
    const int tid  = threadIdx.x;
    const int wid  = tid >> 5;
    const int lane = tid & 31;
    const int wm   = wid >> 1;       // 0..3 (32 q rows each)
    const int wn   = wid & 1;        // 0..1 (32 d cols each)
    const int it = blockIdx.x;
    const int bh = blockIdx.y;
    const int b = bh >> 4, h = bh & 15;

    const __nv_bfloat16* pAh = ph + ((size_t)bh * Sq + it * 128) * Sq;
    const __nv_bfloat16* pAl = pl + ((size_t)bh * Sq + it * 128) * Sq;
    const __nv_bfloat16* pBh = vh + (size_t)bh * DHd * Sq;
    const __nv_bfloat16* pBl = vl + (size_t)bh * DHd * Sq;

    const int lrow = tid >> 3;
    const int lc8  = (tid & 7) * 8;
    const int NB = (it + 1) * 2;     // K = (it+1)*128, BK=64

    float acc[2][4][4];
    #pragma unroll
    for (int i = 0; i < 2; i++)
        #pragma unroll
        for (int j = 0; j < 4; j++)
            #pragma unroll
            for (int q = 0; q < 4; q++) acc[i][j][q] = 0.f;

    // prefetch stage 0
    {
        const uint32_t so = sbase;
        #pragma unroll
        for (int i = 0; i < 4; i++) {
            const int row = lrow + i * 32;
            const uint32_t sa = so + (uint32_t)(row * LDS + lc8) * 2;
            const size_t ga = (size_t)row * Sq + lc8;
            cp16(sa,             pAh + ga);
            cp16(sa + MAT_BYTES, pAl + ga);
        }
        #pragma unroll
        for (int i = 0; i < 2; i++) {
            const int row = lrow + i * 32;
            const uint32_t sa = so + 2*MAT_BYTES + (uint32_t)(row * LDS + lc8) * 2;
            const size_t gb = (size_t)row * Sq + lc8;
            cp16(sa,          pBh + gb);
            cp16(sa + MATB64, pBl + gb);
        }
        CP_COMMIT();
    }

    uint32_t ahf[2][2][4], alf[2][2][4], bhf[2][2][4], blf[2][2][4];

    for (int kb = 0; kb < NB; kb++) {
        const int s = kb & 1;
        if (kb + 1 < NB) {
            const int kk = (kb + 1) * BK;
            const uint32_t so = sbase + (s ^ 1) * PV_STAGE;
            #pragma unroll
            for (int i = 0; i < 4; i++) {
                const int row = lrow + i * 32;
                const uint32_t sa = so + (uint32_t)(row * LDS + lc8) * 2;
                const size_t ga = (size_t)row * Sq + kk + lc8;
                cp16(sa,             pAh + ga);
                cp16(sa + MAT_BYTES, pAl + ga);
            }
            #pragma unroll
            for (int i = 0; i < 2; i++) {
                const int row = lrow + i * 32;
                const uint32_t sa = so + 2*MAT_BYTES + (uint32_t)(row * LDS + lc8) * 2;
                const size_t gb = (size_t)row * Sq + kk + lc8;
                cp16(sa,          pBh + gb);
                cp16(sa + MATB64, pBl + gb);
            }
            CP_COMMIT();
            CP_WAIT(1);
        } else {
            CP_WAIT(0);
        }
        __syncthreads();

        const uint32_t so = sbase + s * PV_STAGE;
        auto load_frags = [&](int k16, int bsel) {
            const int kc = k16 * 16;
            #pragma unroll
            for (int mt = 0; mt < 2; mt++) {
                const int arow = wm * 32 + mt * 16 + (lane & 15);
                const int acol = kc + ((lane >> 4) << 3);
                const uint32_t addr = so + (uint32_t)(arow * LDS + acol) * 2;
                LDSM_X4(ahf[bsel][mt][0], ahf[bsel][mt][1], ahf[bsel][mt][2], ahf[bsel][mt][3], addr);
                LDSM_X4(alf[bsel][mt][0], alf[bsel][mt][1], alf[bsel][mt][2], alf[bsel][mt][3], addr + MAT_BYTES);
            }
            #pragma unroll
            for (int p = 0; p < 2; p++) {
                const int nrow = wn * 32 + p * 16 + (lane & 7) + ((lane & 16) >> 1);
                const int ncol = kc + (lane & 8);
                const uint32_t addr = so + 2*MAT_BYTES + (uint32_t)(nrow * LDS + ncol) * 2;
                LDSM_X4(bhf[bsel][p][0], bhf[bsel][p][1], bhf[bsel][p][2], bhf[bsel][p][3], addr);
                LDSM_X4(blf[bsel][p][0], blf[bsel][p][1], blf[bsel][p][2], blf[bsel][p][3], addr + MATB64);
            }
        };

        load_frags(0, 0);
        #pragma unroll
        for (int k16 = 0; k16 < 4; k16++) {
            const int cur = k16 & 1;
            if (k16 < 3) load_frags(k16 + 1, cur ^ 1);
            #pragma unroll
            for (int mt = 0; mt < 2; mt++) {
                #pragma unroll
                for (int nt = 0; nt < 4; nt++) {
                    const int pr = nt >> 1, ix = (nt & 1) * 2;
                    MMA_BF16(acc[mt][nt], ahf[cur][mt], bhf[cur][pr][ix], bhf[cur][pr][ix+1]);
                    MMA_BF16(acc[mt][nt], alf[cur][mt], bhf[cur][pr][ix], bhf[cur][pr][ix+1]);
                    MMA_BF16(acc[mt][nt], ahf[cur][mt], blf[cur][pr][ix], blf[cur][pr][ix+1]);
                }
            }
        }
        __syncthreads();
    }

    // epilogue: bf16 hi/lo split to [b, s, h*64+d]
    #pragma unroll
    for (int mt = 0; mt < 2; mt++) {
        const int sA = it * 128 + wm * 32 + mt * 16 + (lane >> 2);
        const int sB = sA + 8;
        #pragma unroll
        for (int nt = 0; nt < 4; nt++) {
            const int d = wn * 32 + nt * 8 + (lane & 3) * 2;
            const size_t gA = ((size_t)(b * Sq + sA)) * Dm + h * DHd + d;
            const size_t gB = ((size_t)(b * Sq + sB)) * Dm + h * DHd + d;
            float v0 = acc[mt][nt][0], v1 = acc[mt][nt][1];
            float v2 = acc[mt][nt][2], v3 = acc[mt][nt][3];
            __nv_bfloat16 h0 = __float2bfloat16(v0), h1 = __float2bfloat16(v1);
            __nv_bfloat16 h2 = __float2bfloat16(v2), h3 = __float2bfloat16(v3);
            __nv_bfloat162 hhA; hhA.x = h0; hhA.y = h1;
            __nv_bfloat162 hhB; hhB.x = h2; hhB.y = h3;
            __nv_bfloat162 llA, llB;
            llA.x = __float2bfloat16(v0 - __bfloat162float(h0));
            llA.y = __float2bfloat16(v1 - __bfloat162float(h1));
            llB.x = __float2bfloat16(v2 - __bfloat162float(h2));
            llB.y = __float2bfloat16(v3 - __bfloat162float(h3));
            *(__nv_bfloat162*)(aohi + gA) = hhA;
            *(__nv_bfloat162*)(aolo + gA) = llA;
            *(__nv_bfloat162*)(aohi + gB) = hhB;
            *(__nv_bfloat162*)(aolo + gB) = llB;
        }
    }
}

// ---------------- gate ----------------
__global__ void gate_kernel(const float* __restrict__ h2, const float* __restrict__ gw,
                            const float* __restrict__ gb, float* __restrict__ gate)
{
    const int row = blockIdx.x;
    const int tid = threadIdx.x;
    const int e = tid >> 5, lane = tid & 31;
    const float* hr = h2 + (size_t)row * Dm;
    float s = 0.f;
    for (int k = lane; k < Dm; k += 32) s += hr[k] * gw[k * Ex + e];
    #pragma unroll
    for (int o = 16; o; o >>= 1) s += __shfl_xor_sync(0xffffffffu, s, o);
    __shared__ float lg[Ex];
    if (lane == 0) lg[e] = s + gb[e];
    __syncthreads();
    if (tid == 0) {
        float m = lg[0];
        #pragma unroll
        for (int q = 1; q < Ex; q++) m = fmaxf(m, lg[q]);
        float ex[Ex], sum = 0.f;
        #pragma unroll
        for (int q = 0; q < Ex; q++) { ex[q] = expf(lg[q] - m); sum += ex[q]; }
        const float inv = 1.0f / sum;
        #pragma unroll
        for (int q = 0; q < Ex; q++) gate[(size_t)row * Ex + q] = ex[q] * inv;
    }
}

// ---------------- sum experts + final LayerNorm ----------------
__global__ void redln_kernel(const float* __restrict__ expout, const float* __restrict__ g,
                             const float* __restrict__ b, float* __restrict__ out)
{
    __shared__ float buf[Dm];
    __shared__ float red[256];
    const int row = blockIdx.x;
    const int tid = threadIdx.x;
    float s = 0.f;
    for (int i = tid; i < Dm; i += 256) {
        float v = 0.f;
        #pragma unroll
        for (int e = 0; e < Ex; e++)
            v += expout[(size_t)e * ROWS * Dm + (size_t)row * Dm + i];
        buf[i] = v; s += v;
    }
    red[tid] = s; __syncthreads();
    for (int off = 128; off > 0; off >>= 1) { if (tid < off) red[tid] += red[tid+off]; __syncthreads(); }
    const float mean = red[0] * (1.0f / Dm);
    __syncthreads();
    float s2 = 0.f;
    for (int i = tid; i < Dm; i += 256) { float d = buf[i] - mean; s2 += d * d; }
    red[tid] = s2; __syncthreads();
    for (int off = 128; off > 0; off >>= 1) { if (tid < off) red[tid] += red[tid+off]; __syncthreads(); }
    const float inv = rsqrtf(red[0] * (1.0f / Dm) + 1e-5f);
    for (int i = tid; i < Dm; i += 256)
        out[(size_t)row * Dm + i] = (buf[i] - mean) * inv * g[i] + b[i];
}

// ---------------- launch ----------------
extern "C" void kernel_launch(void* const* d_in, const int* in_sizes, int n_in,
                              void* d_out, int out_size)
{
    const float* x       = (const float*)d_in[0];
    const float* ln_g    = (const float*)d_in[1];
    const float* ln_b    = (const float*)d_in[2];
    const float* Wq      = (const float*)d_in[3];
    const float* Wk      = (const float*)d_in[4];
    const float* Wv      = (const float*)d_in[5];
    const float* q_scale = (const float*)d_in[6];
    const float* k_scale = (const float*)d_in[7];
    const float* Wo      = (const float*)d_in[8];
    const float* gate_w  = (const float*)d_in[9];
    const float* gate_b  = (const float*)d_in[10];
    const float* w1      = (const float*)d_in[11];
    const float* b1      = (const float*)d_in[12];
    const float* w2      = (const float*)d_in[13];
    const float* b2      = (const float*)d_in[14];
    float* out = (float*)d_out;

    __nv_bfloat16 *h1hi, *h1lo, *aohi, *aolo, *h2hi, *h2lo, *hidhi, *hidlo;
    __nv_bfloat16 *qnh, *qnl, *knh, *knl, *vTh, *vTl, *Phi, *Plo;
    __nv_bfloat16 *wqkvThi, *wqkvTlo, *woThi, *woTlo, *w1Thi, *w1Tlo, *w2Thi, *w2Tlo;
    float *qkvf, *logits, *o, *h2, *gate, *expout;
    cudaGetSymbolAddress((void**)&h1hi, g_h1hi);   cudaGetSymbolAddress((void**)&h1lo, g_h1lo);
    cudaGetSymbolAddress((void**)&qkvf, g_qkvf);
    cudaGetSymbolAddress((void**)&qnh, g_qnh);     cudaGetSymbolAddress((void**)&qnl, g_qnl);
    cudaGetSymbolAddress((void**)&knh, g_knh);     cudaGetSymbolAddress((void**)&knl, g_knl);
    cudaGetSymbolAddress((void**)&vTh, g_vTh);     cudaGetSymbolAddress((void**)&vTl, g_vTl);
    cudaGetSymbolAddress((void**)&logits, g_logits);
    cudaGetSymbolAddress((void**)&Phi, g_Phi);     cudaGetSymbolAddress((void**)&Plo, g_Plo);
    cudaGetSymbolAddress((void**)&aohi, g_aohi);   cudaGetSymbolAddress((void**)&aolo, g_aolo);
    cudaGetSymbolAddress((void**)&o, g_o);         cudaGetSymbolAddress((void**)&h2, g_h2);
    cudaGetSymbolAddress((void**)&h2hi, g_h2hi);   cudaGetSymbolAddress((void**)&h2lo, g_h2lo);
    cudaGetSymbolAddress((void**)&gate, g_gate);
    cudaGetSymbolAddress((void**)&hidhi, g_hidhi); cudaGetSymbolAddress((void**)&hidlo, g_hidlo);
    cudaGetSymbolAddress((void**)&expout, g_expout);
    cudaGetSymbolAddress((void**)&wqkvThi, g_wqkvThi); cudaGetSymbolAddress((void**)&wqkvTlo, g_wqkvTlo);
    cudaGetSymbolAddress((void**)&woThi, g_woThi);     cudaGetSymbolAddress((void**)&woTlo, g_woTlo);
    cudaGetSymbolAddress((void**)&w1Thi, g_w1Thi);     cudaGetSymbolAddress((void**)&w1Tlo, g_w1Tlo);
    cudaGetSymbolAddress((void**)&w2Thi, g_w2Thi);     cudaGetSymbolAddress((void**)&w2Tlo, g_w2Tlo);

    cudaFuncSetAttribute(bgemm_kernel<0>, cudaFuncAttributeMaxDynamicSharedMemorySize, SMEM_TOTAL_G);
    cudaFuncSetAttribute(bgemm_kernel<1>, cudaFuncAttributeMaxDynamicSharedMemorySize, SMEM_TOTAL_G);
    cudaFuncSetAttribute(bgemm_kernel<2>, cudaFuncAttributeMaxDynamicSharedMemorySize, SMEM_TOTAL_G);
    cudaFuncSetAttribute(qk_mma_kernel,   cudaFuncAttributeMaxDynamicSharedMemorySize, SMEM_QK);
    cudaFuncSetAttribute(pv_mma_kernel,   cudaFuncAttributeMaxDynamicSharedMemorySize, SMEM_PV);

    // 0. weight prep
    wprep_kernel<<<dim3(Dm/32, Dm/32, 1), dim3(32,8)>>>(Wq, wqkvThi,           wqkvTlo,           Dm, Dm);
    wprep_kernel<<<dim3(Dm/32, Dm/32, 1), dim3(32,8)>>>(Wk, wqkvThi + Dm*Dm,   wqkvTlo + Dm*Dm,   Dm, Dm);
    wprep_kernel<<<dim3(Dm/32, Dm/32, 1), dim3(32,8)>>>(Wv, wqkvThi + 2*Dm*Dm, wqkvTlo + 2*Dm*Dm, Dm, Dm);
    wprep_kernel<<<dim3(Dm/32, Dm/32, 1), dim3(32,8)>>>(Wo, woThi, woTlo, Dm, Dm);
    wprep_kernel<<<dim3(FFd/32, Dm/32, Ex), dim3(32,8)>>>(w1, w1Thi, w1Tlo, Dm, FFd);
    wprep_kernel<<<dim3(Dm/32, FFd/32, Ex), dim3(32,8)>>>(w2, w2Thi, w2Tlo, FFd, Dm);

    // 1. pre-attention LN -> bf16 hi/lo
    ln_kernel<<<ROWS, 256>>>(x, ln_g, ln_b, nullptr, h1hi, h1lo);

    // 2. fused QKV projection
    bgemm_kernel<0><<<dim3(3*Dm/BN, ROWS/BM, 1), 256, SMEM_TOTAL_G>>>(
        h1hi, h1lo, wqkvThi, wqkvTlo, 3*Dm, Dm, 0, 0, 0,
        qkvf, nullptr, nullptr, nullptr, 0, nullptr);

    // 3. l2norm -> bf16 hi/lo; v transpose -> bf16 hi/lo [bh,d,s]
    l2n_kernel<<<(BH*Sq)/8, 256>>>(qkvf, 0,  q_scale, qnh, qnl);
    l2n_kernel<<<(BH*Sq)/8, 256>>>(qkvf, Dm, k_scale, knh, knl);
    vtrans_kernel<<<dim3(Sq/32, DHd/32, BH), dim3(32,8)>>>(qkvf, vTh, vTl);

    // 4. attention on tensor cores
    qk_mma_kernel<<<dim3(36, BH), 256, SMEM_QK>>>(qnh, qnl, knh, knl, logits);
    softmax_kernel<<<BH*Sq, 128>>>(logits, Phi, Plo);
    pv_mma_kernel<<<dim3(Sq/128, BH), 256, SMEM_PV>>>(Phi, Plo, vTh, vTl, aohi, aolo);

    // 5. output projection + mid LN
    bgemm_kernel<0><<<dim3(Dm/BN, ROWS/BM, 1), 256, SMEM_TOTAL_G>>>(
        aohi, aolo, woThi, woTlo, Dm, Dm, 0, 0, 0,
        o, nullptr, nullptr, nullptr, 0, nullptr);
    ln_kernel<<<ROWS, 256>>>(o, ln_g, ln_b, h2, h2hi, h2lo);

    // 6. gate
    gate_kernel<<<ROWS, 256>>>(h2, gate_w, gate_b, gate);

    // 7. MoE GEMM1: gelu(h2 @ w1 + b1) -> hid hi/lo
    bgemm_kernel<1><<<dim3(FFd/BN, ROWS/BM, Ex), 256, SMEM_TOTAL_G>>>(
        h2hi, h2lo, w1Thi, w1Tlo, FFd, Dm,
        0, (long long)FFd*Dm, (long long)ROWS*FFd,
        nullptr, hidhi, hidlo, b1, FFd, nullptr);

    // 8. MoE GEMM2: gate*(hid @ w2 + b2) -> per-expert expout
    bgemm_kernel<2><<<dim3(Dm/BN, ROWS/BM, Ex), 256, SMEM_TOTAL_G>>>(
        hidhi, hidlo, w2Thi, w2Tlo, Dm, FFd,
        (long long)ROWS*FFd, (long long)Dm*FFd, (long long)ROWS*Dm,
        expout, nullptr, nullptr, b2, Dm, gate);

    // 9. sum experts + final LN -> out
    redln_kernel<<<ROWS, 256>>>(expout, ln_g, ln_b, out);
}